// round 15
// baseline (speedup 1.0000x reference)
#include <cuda_runtime.h>
#include <cuda_bf16.h>
#include <cstdint>

// ---------------------------------------------------------------------------
// GATGraphSimilarity: Siamese 2-layer GAT (heads=4 then 1) + mean pool.
// Round 15: gemm2 drops the O-lo term (per-node-random error, pools away;
// weight lo-terms KEPT — their error is systematic), final_write fused into
// agg2 via completion counter, agg2 consume loop unrolled.
// ---------------------------------------------------------------------------

#define NMAX 50000
#define EMAX 800000
#define GNUM 64
#define NEG_SLOPE 0.2f
#define SCAN_CHUNK 4096
#define SCAN_NB ((NMAX + SCAN_CHUNK - 1) / SCAN_CHUNK)

__device__ __nv_bfloat16 g_X16[2][(size_t)NMAX * 128];
__device__ __nv_bfloat16 g_AGG[2][(size_t)NMAX * 512];
__device__ __nv_bfloat16 g_H2 [2][(size_t)NMAX * 64];
__device__ float g_AS  [2][NMAX * 4];
__device__ float g_AD  [2][NMAX * 4];
__device__ int   g_DEG [2][NMAX];
__device__ int   g_ROWPTR[2][NMAX + 1];
__device__ int   g_ECOL[2][EMAX];
__device__ int   g_EIDX[2][EMAX];
__device__ unsigned long long g_LOOK[2][SCAN_NB];
__device__ float g_POOL[2 * GNUM * 64];
__device__ float g_CNT [2 * GNUM];
__device__ int   g_DONE[1];
__device__ float g_P1S [128 * 4];
__device__ float g_P1D [128 * 4];
__device__ __nv_bfloat16 g_W1T_HI[256 * 128];
__device__ __nv_bfloat16 g_W1T_LO[256 * 128];
__device__ __nv_bfloat16 g_W2T_HI[64 * 256];
__device__ __nv_bfloat16 g_W2T_LO[64 * 256];

static inline int cdiv(int a, int b) { return (a + b - 1) / b; }

__device__ __forceinline__ float leaky(float v) {
    return v > 0.0f ? v : NEG_SLOPE * v;
}

__device__ __forceinline__ uint32_t bf2u(__nv_bfloat162 v) {
    return *reinterpret_cast<uint32_t*>(&v);
}

__device__ __forceinline__ void mma16816(float* d, const uint32_t* a, const uint32_t* b) {
    asm volatile(
        "mma.sync.aligned.m16n8k16.row.col.f32.bf16.bf16.f32 "
        "{%0,%1,%2,%3}, {%4,%5,%6,%7}, {%8,%9}, {%0,%1,%2,%3};"
        : "+f"(d[0]), "+f"(d[1]), "+f"(d[2]), "+f"(d[3])
        : "r"(a[0]), "r"(a[1]), "r"(a[2]), "r"(a[3]), "r"(b[0]), "r"(b[1]));
}

// ---------------------------------------------------------------------------
// Setup
// ---------------------------------------------------------------------------
#define SEG1 (256 * 128)
#define SEG2 (64 * 256)
#define SEG3 1024
#define SEG4 (2 * GNUM * 64 + 2 * GNUM)
#define SEG5 (2 * NMAX)
#define SEG6 (2 * SCAN_NB)
#define SETUP_TOTAL (SEG1 + SEG2 + SEG3 + SEG4 + SEG5 + SEG6 + 1)

__global__ void setup_kernel(const float* __restrict__ W1,
                             const float* __restrict__ W2,
                             const float* __restrict__ as1,
                             const float* __restrict__ ad1,
                             __nv_bfloat16* __restrict__ W1TH,
                             __nv_bfloat16* __restrict__ W1TL,
                             __nv_bfloat16* __restrict__ W2TH,
                             __nv_bfloat16* __restrict__ W2TL,
                             float* __restrict__ P1S,
                             float* __restrict__ P1D,
                             float* __restrict__ POOL,
                             float* __restrict__ CNT,
                             int* __restrict__ DEG,
                             unsigned long long* __restrict__ LOOK,
                             int* __restrict__ DONE) {
    int i = blockIdx.x * blockDim.x + threadIdx.x;
    if (i < SEG1) {
        int n = i / 128, k = i % 128;
        float v = W1[(size_t)k * 256 + n];
        __nv_bfloat16 h = __float2bfloat16(v);
        W1TH[i] = h;
        W1TL[i] = __float2bfloat16(v - __bfloat162float(h));
        return;
    }
    i -= SEG1;
    if (i < SEG2) {
        int n = i / 256, k = i % 256;
        float v = W2[(size_t)k * 64 + n];
        __nv_bfloat16 h = __float2bfloat16(v);
        W2TH[i] = h;
        W2TL[i] = __float2bfloat16(v - __bfloat162float(h));
        return;
    }
    i -= SEG2;
    if (i < SEG3) {
        int is_dst = i >> 9;
        int o = i & 511;
        int k = o >> 2, h = o & 3;
        const float* a = is_dst ? ad1 : as1;
        float s = 0.0f;
        #pragma unroll 8
        for (int d = 0; d < 64; d++)
            s += W1[(size_t)k * 256 + h * 64 + d] * a[h * 64 + d];
        (is_dst ? P1D : P1S)[k * 4 + h] = s;
        return;
    }
    i -= SEG3;
    if (i < 2 * GNUM * 64) { POOL[i] = 0.0f; return; }
    i -= 2 * GNUM * 64;
    if (i < 2 * GNUM) { CNT[i] = 0.0f; return; }
    i -= 2 * GNUM;
    if (i < SEG5) { DEG[i] = 0; return; }
    i -= SEG5;
    if (i < SEG6) { LOOK[i] = 0ULL; return; }
    i -= SEG6;
    if (i < 1) DONE[0] = 0;
}

// ---------------------------------------------------------------------------
// Stage1: alphas+X16 (parts 0,1); degree histogram + edge ranks (parts 2,3).
// ---------------------------------------------------------------------------
__global__ void stage1_kernel(const float* __restrict__ x0,
                              const float* __restrict__ x1,
                              const float* __restrict__ P1S,
                              const float* __restrict__ P1D,
                              float* __restrict__ AS,
                              float* __restrict__ AD,
                              __nv_bfloat16* __restrict__ X16,
                              const int* __restrict__ ei0,
                              const int* __restrict__ ei1,
                              int* __restrict__ deg,
                              int* __restrict__ eidx,
                              int n, int E) {
    const int part = blockIdx.y;
    if (part >= 2) {
        int g = part - 2;
        const int* ei = g ? ei1 : ei0;
        int i = blockIdx.x * blockDim.x + threadIdx.x;
        if (i < E) {
            int rank = atomicAdd(&deg[g * NMAX + ei[E + i]], 1);
            eidx[(size_t)g * EMAX + i] = rank;
        }
        return;
    }
    const int g = part;
    const float* x = g ? x1 : x0;
    const int warp = (blockIdx.x * blockDim.x + threadIdx.x) >> 5;
    const int lane = threadIdx.x & 31;
    if (warp >= n) return;
    float4 xv = *(const float4*)&x[(size_t)warp * 128 + lane * 4];
    {
        __nv_bfloat162 p0 = __floats2bfloat162_rn(xv.x, xv.y);
        __nv_bfloat162 p1 = __floats2bfloat162_rn(xv.z, xv.w);
        uint2 u = make_uint2(bf2u(p0), bf2u(p1));
        *(uint2*)&X16[(size_t)g * NMAX * 128 + (size_t)warp * 128 + lane * 4] = u;
    }
    float s[4] = {0.f, 0.f, 0.f, 0.f};
    float d[4] = {0.f, 0.f, 0.f, 0.f};
    const float* xp = (const float*)&xv;
    #pragma unroll
    for (int j = 0; j < 4; j++) {
        float xk = xp[j];
        float4 ps = *(const float4*)&P1S[(lane * 4 + j) * 4];
        float4 pd = *(const float4*)&P1D[(lane * 4 + j) * 4];
        s[0] += xk * ps.x; s[1] += xk * ps.y; s[2] += xk * ps.z; s[3] += xk * ps.w;
        d[0] += xk * pd.x; d[1] += xk * pd.y; d[2] += xk * pd.z; d[3] += xk * pd.w;
    }
    #pragma unroll
    for (int off = 16; off >= 1; off >>= 1) {
        #pragma unroll
        for (int h = 0; h < 4; h++) {
            s[h] += __shfl_xor_sync(0xffffffffu, s[h], off);
            d[h] += __shfl_xor_sync(0xffffffffu, d[h], off);
        }
    }
    if (lane == 0) {
        *(float4*)&AS[(size_t)g * NMAX * 4 + warp * 4] = make_float4(s[0], s[1], s[2], s[3]);
        *(float4*)&AD[(size_t)g * NMAX * 4 + warp * 4] = make_float4(d[0], d[1], d[2], d[3]);
    }
}

// ---------------------------------------------------------------------------
// Decoupled-lookback scan: deg -> rowptr (exclusive).
// ---------------------------------------------------------------------------
__global__ void scan_lookback_kernel(const int* __restrict__ deg,
                                     int* __restrict__ rowptr,
                                     unsigned long long* __restrict__ LOOK,
                                     int n, int nb) {
    __shared__ int thr[256];
    __shared__ int sh_P;
    const int g = blockIdx.y;
    const int b = blockIdx.x;
    const int t = threadIdx.x;
    const int base = b * SCAN_CHUNK + t * 16;
    const int* dg = deg + g * NMAX;
    int* rp = rowptr + g * (NMAX + 1);
    unsigned long long* look = LOOK + g * SCAN_NB;

    int s = 0;
    int dloc[16];
    #pragma unroll
    for (int q = 0; q < 16; q++) {
        int i = base + q;
        dloc[q] = (i < n) ? dg[i] : 0;
        s += dloc[q];
    }
    thr[t] = s;
    __syncthreads();
    #pragma unroll
    for (int off = 1; off < 256; off <<= 1) {
        int v = (t >= off) ? thr[t - off] : 0;
        __syncthreads();
        thr[t] += v;
        __syncthreads();
    }
    const int total = thr[255];

    if (t == 0) {
        int P = 0;
        if (b == 0) {
            atomicExch(&look[0], (2ULL << 32) | (unsigned int)total);
        } else {
            atomicExch(&look[b], (1ULL << 32) | (unsigned int)total);
            int i = b - 1;
            while (true) {
                unsigned long long w;
                do { w = atomicAdd(&look[i], 0ULL); } while ((w >> 32) == 0ULL);
                int v = (int)(w & 0xffffffffULL);
                P += v;
                if ((w >> 32) == 2ULL) break;
                i--;
            }
            atomicExch(&look[b], (2ULL << 32) | (unsigned int)(P + total));
        }
        sh_P = P;
    }
    __syncthreads();

    int offset = sh_P + ((t == 0) ? 0 : thr[t - 1]);
    #pragma unroll
    for (int q = 0; q < 16; q++) {
        int i = base + q;
        if (i < n) {
            rp[i] = offset;
            offset += dloc[q];
        }
    }
    if (b == nb - 1 && t == 255) rp[n] = offset;
}

// fill CSR: atomic-free scatter using precomputed ranks
__global__ void fill_kernel(const int* __restrict__ ei0, const int* __restrict__ ei1,
                            const int* __restrict__ rowptr,
                            const int* __restrict__ eidx,
                            int* __restrict__ ecol, int E) {
    int g = blockIdx.y;
    const int* ei = g ? ei1 : ei0;
    int i = blockIdx.x * blockDim.x + threadIdx.x;
    if (i >= E) return;
    int s = ei[i];
    int d = ei[E + i];
    int slot = rowptr[g * (NMAX + 1) + d] + eidx[(size_t)g * EMAX + i];
    ecol[(size_t)g * EMAX + slot] = s;
}

// ---------------------------------------------------------------------------
// conv1 aggregation: smem-staged lane-parallel edge weights, then gather+FMA.
// ---------------------------------------------------------------------------
__global__ void agg_x_kernel(const int* __restrict__ rowptr,
                             const int* __restrict__ ecol,
                             const float* __restrict__ AS,
                             const float* __restrict__ AD,
                             const __nv_bfloat16* __restrict__ X16,
                             __nv_bfloat16* __restrict__ AGG,
                             int n) {
    __shared__ int    sh_s[8][32];
    __shared__ float4 sh_u[8][32];

    const int g = blockIdx.y;
    const int* rp = rowptr + g * (NMAX + 1);
    const int* ec = ecol + (size_t)g * EMAX;
    const float* as = AS + (size_t)g * NMAX * 4;
    const __nv_bfloat16* X = X16 + (size_t)g * NMAX * 128;
    __nv_bfloat16* agg = AGG + (size_t)g * NMAX * 512;

    const int w = threadIdx.x >> 5;
    const int warp = (blockIdx.x * blockDim.x + threadIdx.x) >> 5;
    const int lane = threadIdx.x & 31;
    if (warp >= n) return;
    const int d = warp;
    const int beg = rp[d];
    const int end = rp[d + 1];

    float4 asv = *(const float4*)&as[d * 4];
    float4 adv = *(const float4*)&AD[(size_t)g * NMAX * 4 + d * 4];
    float den[4];
    den[0] = __expf(leaky(asv.x + adv.x));
    den[1] = __expf(leaky(asv.y + adv.y));
    den[2] = __expf(leaky(asv.z + adv.z));
    den[3] = __expf(leaky(asv.w + adv.w));

    uint2 ux = *(const uint2*)&X[(size_t)d * 128 + lane * 4];
    float2 xd01 = __bfloat1622float2(*(__nv_bfloat162*)&ux.x);
    float2 xd23 = __bfloat1622float2(*(__nv_bfloat162*)&ux.y);

    float acc[4][4];
    #pragma unroll
    for (int h = 0; h < 4; h++) {
        acc[h][0] = den[h] * xd01.x; acc[h][1] = den[h] * xd01.y;
        acc[h][2] = den[h] * xd23.x; acc[h][3] = den[h] * xd23.y;
    }

    for (int jb = beg; jb < end; jb += 32) {
        int m = end - jb;
        if (m > 32) m = 32;
        if (lane < m) {
            int s = ec[jb + lane];
            float4 a = *(const float4*)&as[s * 4];
            float4 u;
            u.x = __expf(leaky(a.x + adv.x));
            u.y = __expf(leaky(a.y + adv.y));
            u.z = __expf(leaky(a.z + adv.z));
            u.w = __expf(leaky(a.w + adv.w));
            sh_s[w][lane] = s;
            sh_u[w][lane] = u;
        }
        __syncwarp();
        #pragma unroll 4
        for (int k = 0; k < m; k++) {
            int ss = sh_s[w][k];
            float4 u = sh_u[w][k];
            den[0] += u.x; den[1] += u.y; den[2] += u.z; den[3] += u.w;
            uint2 q = *(const uint2*)&X[(size_t)ss * 128 + lane * 4];
            float2 f01 = __bfloat1622float2(*(__nv_bfloat162*)&q.x);
            float2 f23 = __bfloat1622float2(*(__nv_bfloat162*)&q.y);
            acc[0][0] += u.x * f01.x; acc[0][1] += u.x * f01.y;
            acc[0][2] += u.x * f23.x; acc[0][3] += u.x * f23.y;
            acc[1][0] += u.y * f01.x; acc[1][1] += u.y * f01.y;
            acc[1][2] += u.y * f23.x; acc[1][3] += u.y * f23.y;
            acc[2][0] += u.z * f01.x; acc[2][1] += u.z * f01.y;
            acc[2][2] += u.z * f23.x; acc[2][3] += u.z * f23.y;
            acc[3][0] += u.w * f01.x; acc[3][1] += u.w * f01.y;
            acc[3][2] += u.w * f23.x; acc[3][3] += u.w * f23.y;
        }
        __syncwarp();
    }

    #pragma unroll
    for (int h = 0; h < 4; h++) {
        float inv = 1.0f / (den[h] + 1e-16f);
        __nv_bfloat162 q0 = __floats2bfloat162_rn(acc[h][0] * inv, acc[h][1] * inv);
        __nv_bfloat162 q1 = __floats2bfloat162_rn(acc[h][2] * inv, acc[h][3] * inv);
        uint2 u = make_uint2(bf2u(q0), bf2u(q1));
        *(uint2*)&agg[(size_t)d * 512 + h * 128 + lane * 4] = u;
    }
}

// ---------------------------------------------------------------------------
// FUSED GEMM, 87KB smem (B1/O overlay, O stored hi-only for gemm2).
// gemm2 terms: Oh@B2h + Oh@B2l (O-lo dropped: per-node error pools away).
// ---------------------------------------------------------------------------
#define SMF_A     0                       // 128x68 words          34816
#define SMF_REG   34816                   // union region          34816
#define SMF_B1H   (SMF_REG)               //   64x68               17408
#define SMF_B1L   (SMF_REG + 17408)       //   64x68               17408
#define SMF_OH    (SMF_REG)               //   128x36              18432
#define SMF_B2H   (SMF_REG + 34816)       //   64x36                9216
#define SMF_B2L   (SMF_B2H + 9216)        //                        9216
#define SMF_ALPHA (SMF_B2H + 18432)       //  256 floats            1024
#define SMF_TOTAL (SMF_ALPHA + 1024)      //                       88064

__global__ __launch_bounds__(256, 2)
void gemm_fused_kernel(const __nv_bfloat16* __restrict__ AGG,
                       const __nv_bfloat16* __restrict__ B1hi,
                       const __nv_bfloat16* __restrict__ B1lo,
                       const float* __restrict__ bias1,
                       const __nv_bfloat16* __restrict__ B2hi,
                       const __nv_bfloat16* __restrict__ B2lo,
                       __nv_bfloat16* __restrict__ H2,
                       const float* __restrict__ a_src,
                       const float* __restrict__ a_dst,
                       float* __restrict__ AS,
                       float* __restrict__ AD,
                       int M) {
    extern __shared__ char smem[];
    uint32_t* Asm = (uint32_t*)(smem + SMF_A);
    uint32_t* B1h = (uint32_t*)(smem + SMF_B1H);
    uint32_t* B1l = (uint32_t*)(smem + SMF_B1L);
    uint32_t* Oh  = (uint32_t*)(smem + SMF_OH);
    uint32_t* B2h = (uint32_t*)(smem + SMF_B2H);
    uint32_t* B2l = (uint32_t*)(smem + SMF_B2L);
    float* alpha_s = (float*)(smem + SMF_ALPHA);
    float* alpha_d = alpha_s + 128;

    const int g = blockIdx.y;
    const __nv_bfloat16* A = AGG + (size_t)g * NMAX * 512;
    __nv_bfloat16* C = H2 + (size_t)g * NMAX * 64;
    float* ASg = AS + (size_t)g * NMAX * 4;
    float* ADg = AD + (size_t)g * NMAX * 4;
    const int tid = threadIdx.x;
    const int lane = tid & 31;
    const int wid = tid >> 5;
    const int warp_m = wid & 3;
    const int warp_n = wid >> 2;
    const int m0 = blockIdx.x * 128;

    float acc2[2][4][4] = {};

    for (int h = 0; h < 4; h++) {
        if (h) __syncthreads();

        #pragma unroll
        for (int q = 0; q < 8; q++) {
            int idx = q * 256 + tid;
            int r = idx >> 4;
            int c8 = idx & 15;
            int gr = m0 + r;
            uint4 v = make_uint4(0u, 0u, 0u, 0u);
            if (gr < M) v = *(const uint4*)&A[(size_t)gr * 512 + h * 128 + c8 * 8];
            *(uint4*)&Asm[r * 68 + c8 * 4] = v;
        }
        #pragma unroll
        for (int q = 0; q < 4; q++) {
            int idx = q * 256 + tid;
            int r = idx >> 4;
            int c8 = idx & 15;
            uint4 vh = *(const uint4*)&B1hi[(size_t)(h * 64 + r) * 128 + c8 * 8];
            uint4 vl = *(const uint4*)&B1lo[(size_t)(h * 64 + r) * 128 + c8 * 8];
            *(uint4*)&B1h[r * 68 + c8 * 4] = vh;
            *(uint4*)&B1l[r * 68 + c8 * 4] = vl;
        }
        #pragma unroll
        for (int q = 0; q < 2; q++) {
            int idx = q * 256 + tid;
            int r = idx >> 3;
            int c8 = idx & 7;
            uint4 vh = *(const uint4*)&B2hi[(size_t)r * 256 + h * 64 + c8 * 8];
            uint4 vl = *(const uint4*)&B2lo[(size_t)r * 256 + h * 64 + c8 * 8];
            *(uint4*)&B2h[r * 36 + c8 * 4] = vh;
            *(uint4*)&B2l[r * 36 + c8 * 4] = vl;
        }
        __syncthreads();

        // gemm1: acc1 = A @ B1 (2-term, weight split kept)
        float acc1[2][4][4] = {};
        #pragma unroll
        for (int ks = 0; ks < 8; ks++) {
            const int kw = ks * 8 + (lane & 3);
            uint32_t ah[2][4], bh[4][2], bl[4][2];
            #pragma unroll
            for (int mt = 0; mt < 2; mt++) {
                int r0 = warp_m * 32 + mt * 16 + (lane >> 2);
                ah[mt][0] = Asm[r0 * 68 + kw];
                ah[mt][1] = Asm[(r0 + 8) * 68 + kw];
                ah[mt][2] = Asm[r0 * 68 + kw + 4];
                ah[mt][3] = Asm[(r0 + 8) * 68 + kw + 4];
            }
            #pragma unroll
            for (int nt = 0; nt < 4; nt++) {
                int n0 = warp_n * 32 + nt * 8 + (lane >> 2);
                bh[nt][0] = B1h[n0 * 68 + kw];
                bh[nt][1] = B1h[n0 * 68 + kw + 4];
                bl[nt][0] = B1l[n0 * 68 + kw];
                bl[nt][1] = B1l[n0 * 68 + kw + 4];
            }
            #pragma unroll
            for (int mt = 0; mt < 2; mt++)
                #pragma unroll
                for (int nt = 0; nt < 4; nt++) {
                    mma16816(acc1[mt][nt], ah[mt], bh[nt]);
                    mma16816(acc1[mt][nt], ah[mt], bl[nt]);
                }
        }
        __syncthreads();   // B1 reads complete before O overwrites the region

        // bias + ELU, bf16 hi into O (overlaying B1)
        #pragma unroll
        for (int mt = 0; mt < 2; mt++) {
            int r0 = warp_m * 32 + mt * 16 + (lane >> 2);
            #pragma unroll
            for (int nt = 0; nt < 4; nt++) {
                int c0 = warp_n * 32 + nt * 8 + (lane & 3) * 2;
                float b0 = __ldg(&bias1[h * 64 + c0]);
                float b1v = __ldg(&bias1[h * 64 + c0 + 1]);
                float* a4 = acc1[mt][nt];
                float v00 = a4[0] + b0, v01 = a4[1] + b1v;
                float v10 = a4[2] + b0, v11 = a4[3] + b1v;
                v00 = v00 > 0.f ? v00 : (__expf(v00) - 1.f);
                v01 = v01 > 0.f ? v01 : (__expf(v01) - 1.f);
                v10 = v10 > 0.f ? v10 : (__expf(v10) - 1.f);
                v11 = v11 > 0.f ? v11 : (__expf(v11) - 1.f);
                int w = warp_n * 16 + nt * 4 + (lane & 3);
                Oh[r0 * 36 + w] = bf2u(__floats2bfloat162_rn(v00, v01));
                Oh[(r0 + 8) * 36 + w] = bf2u(__floats2bfloat162_rn(v10, v11));
            }
        }
        __syncthreads();

        // gemm2 accumulate: acc2 += Oh @ (B2h + B2l)
        #pragma unroll
        for (int ks = 0; ks < 4; ks++) {
            const int kw = ks * 8 + (lane & 3);
            uint32_t aoh[2][4], bh[4][2], bl[4][2];
            #pragma unroll
            for (int mt = 0; mt < 2; mt++) {
                int r0 = warp_m * 32 + mt * 16 + (lane >> 2);
                aoh[mt][0] = Oh[r0 * 36 + kw];
                aoh[mt][1] = Oh[(r0 + 8) * 36 + kw];
                aoh[mt][2] = Oh[r0 * 36 + kw + 4];
                aoh[mt][3] = Oh[(r0 + 8) * 36 + kw + 4];
            }
            #pragma unroll
            for (int nt = 0; nt < 4; nt++) {
                int n0 = warp_n * 32 + nt * 8 + (lane >> 2);
                bh[nt][0] = B2h[n0 * 36 + kw];
                bh[nt][1] = B2h[n0 * 36 + kw + 4];
                bl[nt][0] = B2l[n0 * 36 + kw];
                bl[nt][1] = B2l[n0 * 36 + kw + 4];
            }
            #pragma unroll
            for (int mt = 0; mt < 2; mt++)
                #pragma unroll
                for (int nt = 0; nt < 4; nt++) {
                    mma16816(acc2[mt][nt], aoh[mt], bh[nt]);
                    mma16816(acc2[mt][nt], aoh[mt], bl[nt]);
                }
        }
    }

    __syncthreads();
    if (tid < 128) { alpha_s[tid] = 0.0f; alpha_d[tid] = 0.0f; }
    __syncthreads();

    float sp[4] = {0.f, 0.f, 0.f, 0.f};
    float dp[4] = {0.f, 0.f, 0.f, 0.f};
    #pragma unroll
    for (int mt = 0; mt < 2; mt++) {
        int r0 = warp_m * 32 + mt * 16 + (lane >> 2);
        #pragma unroll
        for (int nt = 0; nt < 4; nt++) {
            int c0 = warp_n * 32 + nt * 8 + (lane & 3) * 2;
            float* a4 = acc2[mt][nt];
            int gr0 = m0 + r0, gr1 = gr0 + 8;
            if (gr0 < M)
                *(__nv_bfloat162*)&C[(size_t)gr0 * 64 + c0] = __floats2bfloat162_rn(a4[0], a4[1]);
            if (gr1 < M)
                *(__nv_bfloat162*)&C[(size_t)gr1 * 64 + c0] = __floats2bfloat162_rn(a4[2], a4[3]);
            float s0 = __ldg(&a_src[c0]);
            float s1 = __ldg(&a_src[c0 + 1]);
            float d0 = __ldg(&a_dst[c0]);
            float d1 = __ldg(&a_dst[c0 + 1]);
            sp[mt * 2]     += a4[0] * s0 + a4[1] * s1;
            sp[mt * 2 + 1] += a4[2] * s0 + a4[3] * s1;
            dp[mt * 2]     += a4[0] * d0 + a4[1] * d1;
            dp[mt * 2 + 1] += a4[2] * d0 + a4[3] * d1;
        }
    }
    #pragma unroll
    for (int i = 0; i < 4; i++) {
        sp[i] += __shfl_xor_sync(0xffffffffu, sp[i], 1);
        sp[i] += __shfl_xor_sync(0xffffffffu, sp[i], 2);
        dp[i] += __shfl_xor_sync(0xffffffffu, dp[i], 1);
        dp[i] += __shfl_xor_sync(0xffffffffu, dp[i], 2);
    }
    if ((lane & 3) == 0) {
        int r0 = warp_m * 32 + (lane >> 2);
        atomicAdd(&alpha_s[r0],      sp[0]);
        atomicAdd(&alpha_s[r0 + 8],  sp[1]);
        atomicAdd(&alpha_s[r0 + 16], sp[2]);
        atomicAdd(&alpha_s[r0 + 24], sp[3]);
        atomicAdd(&alpha_d[r0],      dp[0]);
        atomicAdd(&alpha_d[r0 + 8],  dp[1]);
        atomicAdd(&alpha_d[r0 + 16], dp[2]);
        atomicAdd(&alpha_d[r0 + 24], dp[3]);
    }
    __syncthreads();
    if (tid < 128) {
        int gr = m0 + tid;
        if (gr < M) {
            ASg[gr * 4] = alpha_s[tid];
            ADg[gr * 4] = alpha_d[tid];
        }
    }
}

// ---------------------------------------------------------------------------
// conv2 aggregation + mean pool + fused final write (completion counter).
// ---------------------------------------------------------------------------
__global__ void agg2_pool_kernel(const int* __restrict__ rowptr,
                                 const int* __restrict__ ecol,
                                 const float* __restrict__ AS,
                                 const float* __restrict__ AD,
                                 const __nv_bfloat16* __restrict__ H2,
                                 const float* __restrict__ bias,
                                 const int* __restrict__ bt0,
                                 const int* __restrict__ bt1,
                                 float* __restrict__ POOL,
                                 float* __restrict__ CNT,
                                 int* __restrict__ DONE,
                                 float* __restrict__ out,
                                 int n, int nblocks) {
    __shared__ int sh_last;
    const int g = blockIdx.y;
    const int* rp = rowptr + g * (NMAX + 1);
    const int* ec = ecol + (size_t)g * EMAX;
    const float* as = AS + (size_t)g * NMAX * 4;
    const __nv_bfloat16* H = H2 + (size_t)g * NMAX * 64;
    const int* batch = g ? bt1 : bt0;
    float* pool = POOL + g * GNUM * 64;
    float* cnt = CNT + g * GNUM;

    const int warp = (blockIdx.x * blockDim.x + threadIdx.x) >> 5;
    const int lane = threadIdx.x & 31;

    if (warp < n) {
        const int d = warp;
        const int beg = rp[d];
        const int end = rp[d + 1];

        float ad_d = AD[(size_t)g * NMAX * 4 + d * 4];
        float den = __expf(leaky(as[d * 4] + ad_d));
        float2 hv = __bfloat1622float2(*(const __nv_bfloat162*)&H[(size_t)d * 64 + lane * 2]);
        float a0 = den * hv.x, a1 = den * hv.y;

        for (int jb = beg; jb < end; jb += 32) {
            int m = end - jb;
            if (m > 32) m = 32;
            int s = 0;
            float u = 0.0f;
            if (lane < m) {
                s = ec[jb + lane];
                u = __expf(leaky(as[s * 4] + ad_d));
            }
            #pragma unroll 4
            for (int k = 0; k < m; k++) {
                int ss = __shfl_sync(0xffffffffu, s, k);
                float uk = __shfl_sync(0xffffffffu, u, k);
                den += uk;
                float2 hs = __bfloat1622float2(*(const __nv_bfloat162*)&H[(size_t)ss * 64 + lane * 2]);
                a0 += uk * hs.x;
                a1 += uk * hs.y;
            }
        }
        float inv = 1.0f / (den + 1e-16f);
        float v0 = a0 * inv + bias[lane * 2];
        float v1 = a1 * inv + bias[lane * 2 + 1];
        v0 = v0 > 0.0f ? v0 : (__expf(v0) - 1.0f);
        v1 = v1 > 0.0f ? v1 : (__expf(v1) - 1.0f);
        int grp = batch[d];
        atomicAdd(&pool[grp * 64 + lane * 2], v0);
        atomicAdd(&pool[grp * 64 + lane * 2 + 1], v1);
        if (lane == 0) atomicAdd(&cnt[grp], 1.0f);
    }

    // completion: last block writes the final output
    __threadfence();
    __syncthreads();
    if (threadIdx.x == 0)
        sh_last = (atomicAdd(DONE, 1) == nblocks - 1) ? 1 : 0;
    __syncthreads();
    if (sh_last) {
        for (int i = threadIdx.x; i < 2 * GNUM * 64; i += blockDim.x) {
            float c = CNT[i >> 6];
            out[i] = POOL[i] / fmaxf(c, 1.0f);
        }
    }
}

// ---------------------------------------------------------------------------
// Launch
// ---------------------------------------------------------------------------
extern "C" void kernel_launch(void* const* d_in, const int* in_sizes, int n_in,
                              void* d_out, int out_size) {
    const float* x1  = (const float*)d_in[0];
    const int*   ei1 = (const int*)d_in[1];
    const int*   bt1 = (const int*)d_in[2];
    const float* x2  = (const float*)d_in[3];
    const int*   ei2 = (const int*)d_in[4];
    const int*   bt2 = (const int*)d_in[5];
    const float* W1  = (const float*)d_in[6];
    const float* as1 = (const float*)d_in[7];
    const float* ad1 = (const float*)d_in[8];
    const float* b1  = (const float*)d_in[9];
    const float* W2  = (const float*)d_in[10];
    const float* as2 = (const float*)d_in[11];
    const float* ad2 = (const float*)d_in[12];
    const float* b2  = (const float*)d_in[13];

    const int n = in_sizes[0] / 128;
    const int e = in_sizes[1] / 2;
    const int nb = cdiv(n, SCAN_CHUNK);

    float *AS, *AD, *POOL, *CNT, *P1S, *P1D;
    int *DEG, *ROWPTR, *ECOL, *EIDX, *DONE;
    unsigned long long* LOOK;
    __nv_bfloat16 *X16, *AGG, *H2, *W1TH, *W1TL, *W2TH, *W2TL;
    cudaGetSymbolAddress((void**)&X16,    g_X16);
    cudaGetSymbolAddress((void**)&AGG,    g_AGG);
    cudaGetSymbolAddress((void**)&H2,     g_H2);
    cudaGetSymbolAddress((void**)&AS,     g_AS);
    cudaGetSymbolAddress((void**)&AD,     g_AD);
    cudaGetSymbolAddress((void**)&DEG,    g_DEG);
    cudaGetSymbolAddress((void**)&ROWPTR, g_ROWPTR);
    cudaGetSymbolAddress((void**)&ECOL,   g_ECOL);
    cudaGetSymbolAddress((void**)&EIDX,   g_EIDX);
    cudaGetSymbolAddress((void**)&LOOK,   g_LOOK);
    cudaGetSymbolAddress((void**)&POOL,   g_POOL);
    cudaGetSymbolAddress((void**)&CNT,    g_CNT);
    cudaGetSymbolAddress((void**)&DONE,   g_DONE);
    cudaGetSymbolAddress((void**)&P1S,    g_P1S);
    cudaGetSymbolAddress((void**)&P1D,    g_P1D);
    cudaGetSymbolAddress((void**)&W1TH,   g_W1T_HI);
    cudaGetSymbolAddress((void**)&W1TL,   g_W1T_LO);
    cudaGetSymbolAddress((void**)&W2TH,   g_W2T_HI);
    cudaGetSymbolAddress((void**)&W2TL,   g_W2T_LO);

    cudaFuncSetAttribute(gemm_fused_kernel,
                         cudaFuncAttributeMaxDynamicSharedMemorySize, SMF_TOTAL);

    setup_kernel<<<cdiv(SETUP_TOTAL, 256), 256>>>(W1, W2, as1, ad1,
                                                  W1TH, W1TL, W2TH, W2TL,
                                                  P1S, P1D, POOL, CNT, DEG, LOOK, DONE);
    {
        int gx = cdiv(n, 8);
        if (gx < cdiv(e, 256)) gx = cdiv(e, 256);
        dim3 gs(gx, 4);
        stage1_kernel<<<gs, 256>>>(x1, x2, P1S, P1D, AS, AD, X16,
                                   ei1, ei2, DEG, EIDX, n, e);
    }
    {
        dim3 gs2(nb, 2);
        scan_lookback_kernel<<<gs2, 256>>>(DEG, ROWPTR, LOOK, n, nb);
    }
    {
        dim3 ge2(cdiv(e, 256), 2);
        fill_kernel<<<ge2, 256>>>(ei1, ei2, ROWPTR, EIDX, ECOL, e);
    }
    {
        dim3 ga(cdiv(n, 8), 2);
        agg_x_kernel<<<ga, 256>>>(ROWPTR, ECOL, AS, AD, X16, AGG, n);
    }
    {
        dim3 gg(cdiv(n, 128), 2);
        gemm_fused_kernel<<<gg, 256, SMF_TOTAL>>>(AGG, W1TH, W1TL, b1,
                                                  W2TH, W2TL, H2,
                                                  as2, ad2, AS, AD, n);
    }
    {
        int gx = cdiv(n, 8);
        dim3 ga(gx, 2);
        agg2_pool_kernel<<<ga, 256>>>(ROWPTR, ECOL, AS, AD, H2, b2,
                                      bt1, bt2, POOL, CNT, DONE,
                                      (float*)d_out, n, gx * 2);
    }
}

// round 16
// speedup vs baseline: 1.7009x; 1.7009x over previous
#include <cuda_runtime.h>
#include <cuda_bf16.h>
#include <cstdint>

// ---------------------------------------------------------------------------
// GATGraphSimilarity: Siamese 2-layer GAT (heads=4 then 1) + mean pool.
// Round 16: REVERT the completion-counter fusion (per-block __threadfence +
// single-address atomic cost ~300us). Keep gemm2 O-lo drop (87KB smem) and
// agg2 unroll from round 15.
// ---------------------------------------------------------------------------

#define NMAX 50000
#define EMAX 800000
#define GNUM 64
#define NEG_SLOPE 0.2f
#define SCAN_CHUNK 4096
#define SCAN_NB ((NMAX + SCAN_CHUNK - 1) / SCAN_CHUNK)

__device__ __nv_bfloat16 g_X16[2][(size_t)NMAX * 128];
__device__ __nv_bfloat16 g_AGG[2][(size_t)NMAX * 512];
__device__ __nv_bfloat16 g_H2 [2][(size_t)NMAX * 64];
__device__ float g_AS  [2][NMAX * 4];
__device__ float g_AD  [2][NMAX * 4];
__device__ int   g_DEG [2][NMAX];
__device__ int   g_ROWPTR[2][NMAX + 1];
__device__ int   g_ECOL[2][EMAX];
__device__ int   g_EIDX[2][EMAX];
__device__ unsigned long long g_LOOK[2][SCAN_NB];
__device__ float g_POOL[2 * GNUM * 64];
__device__ float g_CNT [2 * GNUM];
__device__ float g_P1S [128 * 4];
__device__ float g_P1D [128 * 4];
__device__ __nv_bfloat16 g_W1T_HI[256 * 128];
__device__ __nv_bfloat16 g_W1T_LO[256 * 128];
__device__ __nv_bfloat16 g_W2T_HI[64 * 256];
__device__ __nv_bfloat16 g_W2T_LO[64 * 256];

static inline int cdiv(int a, int b) { return (a + b - 1) / b; }

__device__ __forceinline__ float leaky(float v) {
    return v > 0.0f ? v : NEG_SLOPE * v;
}

__device__ __forceinline__ uint32_t bf2u(__nv_bfloat162 v) {
    return *reinterpret_cast<uint32_t*>(&v);
}

__device__ __forceinline__ void mma16816(float* d, const uint32_t* a, const uint32_t* b) {
    asm volatile(
        "mma.sync.aligned.m16n8k16.row.col.f32.bf16.bf16.f32 "
        "{%0,%1,%2,%3}, {%4,%5,%6,%7}, {%8,%9}, {%0,%1,%2,%3};"
        : "+f"(d[0]), "+f"(d[1]), "+f"(d[2]), "+f"(d[3])
        : "r"(a[0]), "r"(a[1]), "r"(a[2]), "r"(a[3]), "r"(b[0]), "r"(b[1]));
}

// ---------------------------------------------------------------------------
// Setup
// ---------------------------------------------------------------------------
#define SEG1 (256 * 128)
#define SEG2 (64 * 256)
#define SEG3 1024
#define SEG4 (2 * GNUM * 64 + 2 * GNUM)
#define SEG5 (2 * NMAX)
#define SEG6 (2 * SCAN_NB)
#define SETUP_TOTAL (SEG1 + SEG2 + SEG3 + SEG4 + SEG5 + SEG6)

__global__ void setup_kernel(const float* __restrict__ W1,
                             const float* __restrict__ W2,
                             const float* __restrict__ as1,
                             const float* __restrict__ ad1,
                             __nv_bfloat16* __restrict__ W1TH,
                             __nv_bfloat16* __restrict__ W1TL,
                             __nv_bfloat16* __restrict__ W2TH,
                             __nv_bfloat16* __restrict__ W2TL,
                             float* __restrict__ P1S,
                             float* __restrict__ P1D,
                             float* __restrict__ POOL,
                             float* __restrict__ CNT,
                             int* __restrict__ DEG,
                             unsigned long long* __restrict__ LOOK) {
    int i = blockIdx.x * blockDim.x + threadIdx.x;
    if (i < SEG1) {
        int n = i / 128, k = i % 128;
        float v = W1[(size_t)k * 256 + n];
        __nv_bfloat16 h = __float2bfloat16(v);
        W1TH[i] = h;
        W1TL[i] = __float2bfloat16(v - __bfloat162float(h));
        return;
    }
    i -= SEG1;
    if (i < SEG2) {
        int n = i / 256, k = i % 256;
        float v = W2[(size_t)k * 64 + n];
        __nv_bfloat16 h = __float2bfloat16(v);
        W2TH[i] = h;
        W2TL[i] = __float2bfloat16(v - __bfloat162float(h));
        return;
    }
    i -= SEG2;
    if (i < SEG3) {
        int is_dst = i >> 9;
        int o = i & 511;
        int k = o >> 2, h = o & 3;
        const float* a = is_dst ? ad1 : as1;
        float s = 0.0f;
        #pragma unroll 8
        for (int d = 0; d < 64; d++)
            s += W1[(size_t)k * 256 + h * 64 + d] * a[h * 64 + d];
        (is_dst ? P1D : P1S)[k * 4 + h] = s;
        return;
    }
    i -= SEG3;
    if (i < 2 * GNUM * 64) { POOL[i] = 0.0f; return; }
    i -= 2 * GNUM * 64;
    if (i < 2 * GNUM) { CNT[i] = 0.0f; return; }
    i -= 2 * GNUM;
    if (i < SEG5) { DEG[i] = 0; return; }
    i -= SEG5;
    if (i < SEG6) LOOK[i] = 0ULL;
}

// ---------------------------------------------------------------------------
// Stage1: alphas+X16 (parts 0,1); degree histogram + edge ranks (parts 2,3).
// ---------------------------------------------------------------------------
__global__ void stage1_kernel(const float* __restrict__ x0,
                              const float* __restrict__ x1,
                              const float* __restrict__ P1S,
                              const float* __restrict__ P1D,
                              float* __restrict__ AS,
                              float* __restrict__ AD,
                              __nv_bfloat16* __restrict__ X16,
                              const int* __restrict__ ei0,
                              const int* __restrict__ ei1,
                              int* __restrict__ deg,
                              int* __restrict__ eidx,
                              int n, int E) {
    const int part = blockIdx.y;
    if (part >= 2) {
        int g = part - 2;
        const int* ei = g ? ei1 : ei0;
        int i = blockIdx.x * blockDim.x + threadIdx.x;
        if (i < E) {
            int rank = atomicAdd(&deg[g * NMAX + ei[E + i]], 1);
            eidx[(size_t)g * EMAX + i] = rank;
        }
        return;
    }
    const int g = part;
    const float* x = g ? x1 : x0;
    const int warp = (blockIdx.x * blockDim.x + threadIdx.x) >> 5;
    const int lane = threadIdx.x & 31;
    if (warp >= n) return;
    float4 xv = *(const float4*)&x[(size_t)warp * 128 + lane * 4];
    {
        __nv_bfloat162 p0 = __floats2bfloat162_rn(xv.x, xv.y);
        __nv_bfloat162 p1 = __floats2bfloat162_rn(xv.z, xv.w);
        uint2 u = make_uint2(bf2u(p0), bf2u(p1));
        *(uint2*)&X16[(size_t)g * NMAX * 128 + (size_t)warp * 128 + lane * 4] = u;
    }
    float s[4] = {0.f, 0.f, 0.f, 0.f};
    float d[4] = {0.f, 0.f, 0.f, 0.f};
    const float* xp = (const float*)&xv;
    #pragma unroll
    for (int j = 0; j < 4; j++) {
        float xk = xp[j];
        float4 ps = *(const float4*)&P1S[(lane * 4 + j) * 4];
        float4 pd = *(const float4*)&P1D[(lane * 4 + j) * 4];
        s[0] += xk * ps.x; s[1] += xk * ps.y; s[2] += xk * ps.z; s[3] += xk * ps.w;
        d[0] += xk * pd.x; d[1] += xk * pd.y; d[2] += xk * pd.z; d[3] += xk * pd.w;
    }
    #pragma unroll
    for (int off = 16; off >= 1; off >>= 1) {
        #pragma unroll
        for (int h = 0; h < 4; h++) {
            s[h] += __shfl_xor_sync(0xffffffffu, s[h], off);
            d[h] += __shfl_xor_sync(0xffffffffu, d[h], off);
        }
    }
    if (lane == 0) {
        *(float4*)&AS[(size_t)g * NMAX * 4 + warp * 4] = make_float4(s[0], s[1], s[2], s[3]);
        *(float4*)&AD[(size_t)g * NMAX * 4 + warp * 4] = make_float4(d[0], d[1], d[2], d[3]);
    }
}

// ---------------------------------------------------------------------------
// Decoupled-lookback scan: deg -> rowptr (exclusive).
// ---------------------------------------------------------------------------
__global__ void scan_lookback_kernel(const int* __restrict__ deg,
                                     int* __restrict__ rowptr,
                                     unsigned long long* __restrict__ LOOK,
                                     int n, int nb) {
    __shared__ int thr[256];
    __shared__ int sh_P;
    const int g = blockIdx.y;
    const int b = blockIdx.x;
    const int t = threadIdx.x;
    const int base = b * SCAN_CHUNK + t * 16;
    const int* dg = deg + g * NMAX;
    int* rp = rowptr + g * (NMAX + 1);
    unsigned long long* look = LOOK + g * SCAN_NB;

    int s = 0;
    int dloc[16];
    #pragma unroll
    for (int q = 0; q < 16; q++) {
        int i = base + q;
        dloc[q] = (i < n) ? dg[i] : 0;
        s += dloc[q];
    }
    thr[t] = s;
    __syncthreads();
    #pragma unroll
    for (int off = 1; off < 256; off <<= 1) {
        int v = (t >= off) ? thr[t - off] : 0;
        __syncthreads();
        thr[t] += v;
        __syncthreads();
    }
    const int total = thr[255];

    if (t == 0) {
        int P = 0;
        if (b == 0) {
            atomicExch(&look[0], (2ULL << 32) | (unsigned int)total);
        } else {
            atomicExch(&look[b], (1ULL << 32) | (unsigned int)total);
            int i = b - 1;
            while (true) {
                unsigned long long w;
                do { w = atomicAdd(&look[i], 0ULL); } while ((w >> 32) == 0ULL);
                int v = (int)(w & 0xffffffffULL);
                P += v;
                if ((w >> 32) == 2ULL) break;
                i--;
            }
            atomicExch(&look[b], (2ULL << 32) | (unsigned int)(P + total));
        }
        sh_P = P;
    }
    __syncthreads();

    int offset = sh_P + ((t == 0) ? 0 : thr[t - 1]);
    #pragma unroll
    for (int q = 0; q < 16; q++) {
        int i = base + q;
        if (i < n) {
            rp[i] = offset;
            offset += dloc[q];
        }
    }
    if (b == nb - 1 && t == 255) rp[n] = offset;
}

// fill CSR: atomic-free scatter using precomputed ranks
__global__ void fill_kernel(const int* __restrict__ ei0, const int* __restrict__ ei1,
                            const int* __restrict__ rowptr,
                            const int* __restrict__ eidx,
                            int* __restrict__ ecol, int E) {
    int g = blockIdx.y;
    const int* ei = g ? ei1 : ei0;
    int i = blockIdx.x * blockDim.x + threadIdx.x;
    if (i >= E) return;
    int s = ei[i];
    int d = ei[E + i];
    int slot = rowptr[g * (NMAX + 1) + d] + eidx[(size_t)g * EMAX + i];
    ecol[(size_t)g * EMAX + slot] = s;
}

// ---------------------------------------------------------------------------
// conv1 aggregation: smem-staged lane-parallel edge weights, then gather+FMA.
// ---------------------------------------------------------------------------
__global__ void agg_x_kernel(const int* __restrict__ rowptr,
                             const int* __restrict__ ecol,
                             const float* __restrict__ AS,
                             const float* __restrict__ AD,
                             const __nv_bfloat16* __restrict__ X16,
                             __nv_bfloat16* __restrict__ AGG,
                             int n) {
    __shared__ int    sh_s[8][32];
    __shared__ float4 sh_u[8][32];

    const int g = blockIdx.y;
    const int* rp = rowptr + g * (NMAX + 1);
    const int* ec = ecol + (size_t)g * EMAX;
    const float* as = AS + (size_t)g * NMAX * 4;
    const __nv_bfloat16* X = X16 + (size_t)g * NMAX * 128;
    __nv_bfloat16* agg = AGG + (size_t)g * NMAX * 512;

    const int w = threadIdx.x >> 5;
    const int warp = (blockIdx.x * blockDim.x + threadIdx.x) >> 5;
    const int lane = threadIdx.x & 31;
    if (warp >= n) return;
    const int d = warp;
    const int beg = rp[d];
    const int end = rp[d + 1];

    float4 asv = *(const float4*)&as[d * 4];
    float4 adv = *(const float4*)&AD[(size_t)g * NMAX * 4 + d * 4];
    float den[4];
    den[0] = __expf(leaky(asv.x + adv.x));
    den[1] = __expf(leaky(asv.y + adv.y));
    den[2] = __expf(leaky(asv.z + adv.z));
    den[3] = __expf(leaky(asv.w + adv.w));

    uint2 ux = *(const uint2*)&X[(size_t)d * 128 + lane * 4];
    float2 xd01 = __bfloat1622float2(*(__nv_bfloat162*)&ux.x);
    float2 xd23 = __bfloat1622float2(*(__nv_bfloat162*)&ux.y);

    float acc[4][4];
    #pragma unroll
    for (int h = 0; h < 4; h++) {
        acc[h][0] = den[h] * xd01.x; acc[h][1] = den[h] * xd01.y;
        acc[h][2] = den[h] * xd23.x; acc[h][3] = den[h] * xd23.y;
    }

    for (int jb = beg; jb < end; jb += 32) {
        int m = end - jb;
        if (m > 32) m = 32;
        if (lane < m) {
            int s = ec[jb + lane];
            float4 a = *(const float4*)&as[s * 4];
            float4 u;
            u.x = __expf(leaky(a.x + adv.x));
            u.y = __expf(leaky(a.y + adv.y));
            u.z = __expf(leaky(a.z + adv.z));
            u.w = __expf(leaky(a.w + adv.w));
            sh_s[w][lane] = s;
            sh_u[w][lane] = u;
        }
        __syncwarp();
        #pragma unroll 4
        for (int k = 0; k < m; k++) {
            int ss = sh_s[w][k];
            float4 u = sh_u[w][k];
            den[0] += u.x; den[1] += u.y; den[2] += u.z; den[3] += u.w;
            uint2 q = *(const uint2*)&X[(size_t)ss * 128 + lane * 4];
            float2 f01 = __bfloat1622float2(*(__nv_bfloat162*)&q.x);
            float2 f23 = __bfloat1622float2(*(__nv_bfloat162*)&q.y);
            acc[0][0] += u.x * f01.x; acc[0][1] += u.x * f01.y;
            acc[0][2] += u.x * f23.x; acc[0][3] += u.x * f23.y;
            acc[1][0] += u.y * f01.x; acc[1][1] += u.y * f01.y;
            acc[1][2] += u.y * f23.x; acc[1][3] += u.y * f23.y;
            acc[2][0] += u.z * f01.x; acc[2][1] += u.z * f01.y;
            acc[2][2] += u.z * f23.x; acc[2][3] += u.z * f23.y;
            acc[3][0] += u.w * f01.x; acc[3][1] += u.w * f01.y;
            acc[3][2] += u.w * f23.x; acc[3][3] += u.w * f23.y;
        }
        __syncwarp();
    }

    #pragma unroll
    for (int h = 0; h < 4; h++) {
        float inv = 1.0f / (den[h] + 1e-16f);
        __nv_bfloat162 q0 = __floats2bfloat162_rn(acc[h][0] * inv, acc[h][1] * inv);
        __nv_bfloat162 q1 = __floats2bfloat162_rn(acc[h][2] * inv, acc[h][3] * inv);
        uint2 u = make_uint2(bf2u(q0), bf2u(q1));
        *(uint2*)&agg[(size_t)d * 512 + h * 128 + lane * 4] = u;
    }
}

// ---------------------------------------------------------------------------
// FUSED GEMM, 87KB smem (B1/O overlay, O stored hi-only for gemm2).
// ---------------------------------------------------------------------------
#define SMF_A     0                       // 128x68 words          34816
#define SMF_REG   34816                   // union region          34816
#define SMF_B1H   (SMF_REG)
#define SMF_B1L   (SMF_REG + 17408)
#define SMF_OH    (SMF_REG)
#define SMF_B2H   (SMF_REG + 34816)
#define SMF_B2L   (SMF_B2H + 9216)
#define SMF_ALPHA (SMF_B2H + 18432)
#define SMF_TOTAL (SMF_ALPHA + 1024)      // 88064

__global__ __launch_bounds__(256, 2)
void gemm_fused_kernel(const __nv_bfloat16* __restrict__ AGG,
                       const __nv_bfloat16* __restrict__ B1hi,
                       const __nv_bfloat16* __restrict__ B1lo,
                       const float* __restrict__ bias1,
                       const __nv_bfloat16* __restrict__ B2hi,
                       const __nv_bfloat16* __restrict__ B2lo,
                       __nv_bfloat16* __restrict__ H2,
                       const float* __restrict__ a_src,
                       const float* __restrict__ a_dst,
                       float* __restrict__ AS,
                       float* __restrict__ AD,
                       int M) {
    extern __shared__ char smem[];
    uint32_t* Asm = (uint32_t*)(smem + SMF_A);
    uint32_t* B1h = (uint32_t*)(smem + SMF_B1H);
    uint32_t* B1l = (uint32_t*)(smem + SMF_B1L);
    uint32_t* Oh  = (uint32_t*)(smem + SMF_OH);
    uint32_t* B2h = (uint32_t*)(smem + SMF_B2H);
    uint32_t* B2l = (uint32_t*)(smem + SMF_B2L);
    float* alpha_s = (float*)(smem + SMF_ALPHA);
    float* alpha_d = alpha_s + 128;

    const int g = blockIdx.y;
    const __nv_bfloat16* A = AGG + (size_t)g * NMAX * 512;
    __nv_bfloat16* C = H2 + (size_t)g * NMAX * 64;
    float* ASg = AS + (size_t)g * NMAX * 4;
    float* ADg = AD + (size_t)g * NMAX * 4;
    const int tid = threadIdx.x;
    const int lane = tid & 31;
    const int wid = tid >> 5;
    const int warp_m = wid & 3;
    const int warp_n = wid >> 2;
    const int m0 = blockIdx.x * 128;

    float acc2[2][4][4] = {};

    for (int h = 0; h < 4; h++) {
        if (h) __syncthreads();

        #pragma unroll
        for (int q = 0; q < 8; q++) {
            int idx = q * 256 + tid;
            int r = idx >> 4;
            int c8 = idx & 15;
            int gr = m0 + r;
            uint4 v = make_uint4(0u, 0u, 0u, 0u);
            if (gr < M) v = *(const uint4*)&A[(size_t)gr * 512 + h * 128 + c8 * 8];
            *(uint4*)&Asm[r * 68 + c8 * 4] = v;
        }
        #pragma unroll
        for (int q = 0; q < 4; q++) {
            int idx = q * 256 + tid;
            int r = idx >> 4;
            int c8 = idx & 15;
            uint4 vh = *(const uint4*)&B1hi[(size_t)(h * 64 + r) * 128 + c8 * 8];
            uint4 vl = *(const uint4*)&B1lo[(size_t)(h * 64 + r) * 128 + c8 * 8];
            *(uint4*)&B1h[r * 68 + c8 * 4] = vh;
            *(uint4*)&B1l[r * 68 + c8 * 4] = vl;
        }
        #pragma unroll
        for (int q = 0; q < 2; q++) {
            int idx = q * 256 + tid;
            int r = idx >> 3;
            int c8 = idx & 7;
            uint4 vh = *(const uint4*)&B2hi[(size_t)r * 256 + h * 64 + c8 * 8];
            uint4 vl = *(const uint4*)&B2lo[(size_t)r * 256 + h * 64 + c8 * 8];
            *(uint4*)&B2h[r * 36 + c8 * 4] = vh;
            *(uint4*)&B2l[r * 36 + c8 * 4] = vl;
        }
        __syncthreads();

        // gemm1: acc1 = A @ B1 (2-term, weight split kept)
        float acc1[2][4][4] = {};
        #pragma unroll
        for (int ks = 0; ks < 8; ks++) {
            const int kw = ks * 8 + (lane & 3);
            uint32_t ah[2][4], bh[4][2], bl[4][2];
            #pragma unroll
            for (int mt = 0; mt < 2; mt++) {
                int r0 = warp_m * 32 + mt * 16 + (lane >> 2);
                ah[mt][0] = Asm[r0 * 68 + kw];
                ah[mt][1] = Asm[(r0 + 8) * 68 + kw];
                ah[mt][2] = Asm[r0 * 68 + kw + 4];
                ah[mt][3] = Asm[(r0 + 8) * 68 + kw + 4];
            }
            #pragma unroll
            for (int nt = 0; nt < 4; nt++) {
                int n0 = warp_n * 32 + nt * 8 + (lane >> 2);
                bh[nt][0] = B1h[n0 * 68 + kw];
                bh[nt][1] = B1h[n0 * 68 + kw + 4];
                bl[nt][0] = B1l[n0 * 68 + kw];
                bl[nt][1] = B1l[n0 * 68 + kw + 4];
            }
            #pragma unroll
            for (int mt = 0; mt < 2; mt++)
                #pragma unroll
                for (int nt = 0; nt < 4; nt++) {
                    mma16816(acc1[mt][nt], ah[mt], bh[nt]);
                    mma16816(acc1[mt][nt], ah[mt], bl[nt]);
                }
        }
        __syncthreads();   // B1 reads complete before O overwrites the region

        // bias + ELU, bf16 hi into O (overlaying B1)
        #pragma unroll
        for (int mt = 0; mt < 2; mt++) {
            int r0 = warp_m * 32 + mt * 16 + (lane >> 2);
            #pragma unroll
            for (int nt = 0; nt < 4; nt++) {
                int c0 = warp_n * 32 + nt * 8 + (lane & 3) * 2;
                float b0 = __ldg(&bias1[h * 64 + c0]);
                float b1v = __ldg(&bias1[h * 64 + c0 + 1]);
                float* a4 = acc1[mt][nt];
                float v00 = a4[0] + b0, v01 = a4[1] + b1v;
                float v10 = a4[2] + b0, v11 = a4[3] + b1v;
                v00 = v00 > 0.f ? v00 : (__expf(v00) - 1.f);
                v01 = v01 > 0.f ? v01 : (__expf(v01) - 1.f);
                v10 = v10 > 0.f ? v10 : (__expf(v10) - 1.f);
                v11 = v11 > 0.f ? v11 : (__expf(v11) - 1.f);
                int w = warp_n * 16 + nt * 4 + (lane & 3);
                Oh[r0 * 36 + w] = bf2u(__floats2bfloat162_rn(v00, v01));
                Oh[(r0 + 8) * 36 + w] = bf2u(__floats2bfloat162_rn(v10, v11));
            }
        }
        __syncthreads();

        // gemm2 accumulate: acc2 += Oh @ (B2h + B2l)
        #pragma unroll
        for (int ks = 0; ks < 4; ks++) {
            const int kw = ks * 8 + (lane & 3);
            uint32_t aoh[2][4], bh[4][2], bl[4][2];
            #pragma unroll
            for (int mt = 0; mt < 2; mt++) {
                int r0 = warp_m * 32 + mt * 16 + (lane >> 2);
                aoh[mt][0] = Oh[r0 * 36 + kw];
                aoh[mt][1] = Oh[(r0 + 8) * 36 + kw];
                aoh[mt][2] = Oh[r0 * 36 + kw + 4];
                aoh[mt][3] = Oh[(r0 + 8) * 36 + kw + 4];
            }
            #pragma unroll
            for (int nt = 0; nt < 4; nt++) {
                int n0 = warp_n * 32 + nt * 8 + (lane >> 2);
                bh[nt][0] = B2h[n0 * 36 + kw];
                bh[nt][1] = B2h[n0 * 36 + kw + 4];
                bl[nt][0] = B2l[n0 * 36 + kw];
                bl[nt][1] = B2l[n0 * 36 + kw + 4];
            }
            #pragma unroll
            for (int mt = 0; mt < 2; mt++)
                #pragma unroll
                for (int nt = 0; nt < 4; nt++) {
                    mma16816(acc2[mt][nt], aoh[mt], bh[nt]);
                    mma16816(acc2[mt][nt], aoh[mt], bl[nt]);
                }
        }
    }

    __syncthreads();
    if (tid < 128) { alpha_s[tid] = 0.0f; alpha_d[tid] = 0.0f; }
    __syncthreads();

    float sp[4] = {0.f, 0.f, 0.f, 0.f};
    float dp[4] = {0.f, 0.f, 0.f, 0.f};
    #pragma unroll
    for (int mt = 0; mt < 2; mt++) {
        int r0 = warp_m * 32 + mt * 16 + (lane >> 2);
        #pragma unroll
        for (int nt = 0; nt < 4; nt++) {
            int c0 = warp_n * 32 + nt * 8 + (lane & 3) * 2;
            float* a4 = acc2[mt][nt];
            int gr0 = m0 + r0, gr1 = gr0 + 8;
            if (gr0 < M)
                *(__nv_bfloat162*)&C[(size_t)gr0 * 64 + c0] = __floats2bfloat162_rn(a4[0], a4[1]);
            if (gr1 < M)
                *(__nv_bfloat162*)&C[(size_t)gr1 * 64 + c0] = __floats2bfloat162_rn(a4[2], a4[3]);
            float s0 = __ldg(&a_src[c0]);
            float s1 = __ldg(&a_src[c0 + 1]);
            float d0 = __ldg(&a_dst[c0]);
            float d1 = __ldg(&a_dst[c0 + 1]);
            sp[mt * 2]     += a4[0] * s0 + a4[1] * s1;
            sp[mt * 2 + 1] += a4[2] * s0 + a4[3] * s1;
            dp[mt * 2]     += a4[0] * d0 + a4[1] * d1;
            dp[mt * 2 + 1] += a4[2] * d0 + a4[3] * d1;
        }
    }
    #pragma unroll
    for (int i = 0; i < 4; i++) {
        sp[i] += __shfl_xor_sync(0xffffffffu, sp[i], 1);
        sp[i] += __shfl_xor_sync(0xffffffffu, sp[i], 2);
        dp[i] += __shfl_xor_sync(0xffffffffu, dp[i], 1);
        dp[i] += __shfl_xor_sync(0xffffffffu, dp[i], 2);
    }
    if ((lane & 3) == 0) {
        int r0 = warp_m * 32 + (lane >> 2);
        atomicAdd(&alpha_s[r0],      sp[0]);
        atomicAdd(&alpha_s[r0 + 8],  sp[1]);
        atomicAdd(&alpha_s[r0 + 16], sp[2]);
        atomicAdd(&alpha_s[r0 + 24], sp[3]);
        atomicAdd(&alpha_d[r0],      dp[0]);
        atomicAdd(&alpha_d[r0 + 8],  dp[1]);
        atomicAdd(&alpha_d[r0 + 16], dp[2]);
        atomicAdd(&alpha_d[r0 + 24], dp[3]);
    }
    __syncthreads();
    if (tid < 128) {
        int gr = m0 + tid;
        if (gr < M) {
            ASg[gr * 4] = alpha_s[tid];
            ADg[gr * 4] = alpha_d[tid];
        }
    }
}

// ---------------------------------------------------------------------------
// conv2 aggregation with in-warp lane-parallel edge weights + mean pool.
// ---------------------------------------------------------------------------
__global__ void agg2_pool_kernel(const int* __restrict__ rowptr,
                                 const int* __restrict__ ecol,
                                 const float* __restrict__ AS,
                                 const float* __restrict__ AD,
                                 const __nv_bfloat16* __restrict__ H2,
                                 const float* __restrict__ bias,
                                 const int* __restrict__ bt0,
                                 const int* __restrict__ bt1,
                                 float* __restrict__ POOL,
                                 float* __restrict__ CNT,
                                 int n) {
    const int g = blockIdx.y;
    const int* rp = rowptr + g * (NMAX + 1);
    const int* ec = ecol + (size_t)g * EMAX;
    const float* as = AS + (size_t)g * NMAX * 4;
    const __nv_bfloat16* H = H2 + (size_t)g * NMAX * 64;
    const int* batch = g ? bt1 : bt0;
    float* pool = POOL + g * GNUM * 64;
    float* cnt = CNT + g * GNUM;

    const int warp = (blockIdx.x * blockDim.x + threadIdx.x) >> 5;
    const int lane = threadIdx.x & 31;
    if (warp >= n) return;
    const int d = warp;
    const int beg = rp[d];
    const int end = rp[d + 1];

    float ad_d = AD[(size_t)g * NMAX * 4 + d * 4];
    float den = __expf(leaky(as[d * 4] + ad_d));
    float2 hv = __bfloat1622float2(*(const __nv_bfloat162*)&H[(size_t)d * 64 + lane * 2]);
    float a0 = den * hv.x, a1 = den * hv.y;

    for (int jb = beg; jb < end; jb += 32) {
        int m = end - jb;
        if (m > 32) m = 32;
        int s = 0;
        float u = 0.0f;
        if (lane < m) {
            s = ec[jb + lane];
            u = __expf(leaky(as[s * 4] + ad_d));
        }
        #pragma unroll 4
        for (int k = 0; k < m; k++) {
            int ss = __shfl_sync(0xffffffffu, s, k);
            float uk = __shfl_sync(0xffffffffu, u, k);
            den += uk;
            float2 hs = __bfloat1622float2(*(const __nv_bfloat162*)&H[(size_t)ss * 64 + lane * 2]);
            a0 += uk * hs.x;
            a1 += uk * hs.y;
        }
    }
    float inv = 1.0f / (den + 1e-16f);
    float v0 = a0 * inv + bias[lane * 2];
    float v1 = a1 * inv + bias[lane * 2 + 1];
    v0 = v0 > 0.0f ? v0 : (__expf(v0) - 1.0f);
    v1 = v1 > 0.0f ? v1 : (__expf(v1) - 1.0f);
    int grp = batch[d];
    atomicAdd(&pool[grp * 64 + lane * 2], v0);
    atomicAdd(&pool[grp * 64 + lane * 2 + 1], v1);
    if (lane == 0) atomicAdd(&cnt[grp], 1.0f);
}

__global__ void final_write_kernel(const float* __restrict__ POOL,
                                   const float* __restrict__ CNT,
                                   float* __restrict__ out) {
    int i = blockIdx.x * blockDim.x + threadIdx.x;
    if (i >= 2 * GNUM * 64) return;
    float c = CNT[i >> 6];
    out[i] = POOL[i] / fmaxf(c, 1.0f);
}

// ---------------------------------------------------------------------------
// Launch
// ---------------------------------------------------------------------------
extern "C" void kernel_launch(void* const* d_in, const int* in_sizes, int n_in,
                              void* d_out, int out_size) {
    const float* x1  = (const float*)d_in[0];
    const int*   ei1 = (const int*)d_in[1];
    const int*   bt1 = (const int*)d_in[2];
    const float* x2  = (const float*)d_in[3];
    const int*   ei2 = (const int*)d_in[4];
    const int*   bt2 = (const int*)d_in[5];
    const float* W1  = (const float*)d_in[6];
    const float* as1 = (const float*)d_in[7];
    const float* ad1 = (const float*)d_in[8];
    const float* b1  = (const float*)d_in[9];
    const float* W2  = (const float*)d_in[10];
    const float* as2 = (const float*)d_in[11];
    const float* ad2 = (const float*)d_in[12];
    const float* b2  = (const float*)d_in[13];

    const int n = in_sizes[0] / 128;
    const int e = in_sizes[1] / 2;
    const int nb = cdiv(n, SCAN_CHUNK);

    float *AS, *AD, *POOL, *CNT, *P1S, *P1D;
    int *DEG, *ROWPTR, *ECOL, *EIDX;
    unsigned long long* LOOK;
    __nv_bfloat16 *X16, *AGG, *H2, *W1TH, *W1TL, *W2TH, *W2TL;
    cudaGetSymbolAddress((void**)&X16,    g_X16);
    cudaGetSymbolAddress((void**)&AGG,    g_AGG);
    cudaGetSymbolAddress((void**)&H2,     g_H2);
    cudaGetSymbolAddress((void**)&AS,     g_AS);
    cudaGetSymbolAddress((void**)&AD,     g_AD);
    cudaGetSymbolAddress((void**)&DEG,    g_DEG);
    cudaGetSymbolAddress((void**)&ROWPTR, g_ROWPTR);
    cudaGetSymbolAddress((void**)&ECOL,   g_ECOL);
    cudaGetSymbolAddress((void**)&EIDX,   g_EIDX);
    cudaGetSymbolAddress((void**)&LOOK,   g_LOOK);
    cudaGetSymbolAddress((void**)&POOL,   g_POOL);
    cudaGetSymbolAddress((void**)&CNT,    g_CNT);
    cudaGetSymbolAddress((void**)&P1S,    g_P1S);
    cudaGetSymbolAddress((void**)&P1D,    g_P1D);
    cudaGetSymbolAddress((void**)&W1TH,   g_W1T_HI);
    cudaGetSymbolAddress((void**)&W1TL,   g_W1T_LO);
    cudaGetSymbolAddress((void**)&W2TH,   g_W2T_HI);
    cudaGetSymbolAddress((void**)&W2TL,   g_W2T_LO);

    cudaFuncSetAttribute(gemm_fused_kernel,
                         cudaFuncAttributeMaxDynamicSharedMemorySize, SMF_TOTAL);

    setup_kernel<<<cdiv(SETUP_TOTAL, 256), 256>>>(W1, W2, as1, ad1,
                                                  W1TH, W1TL, W2TH, W2TL,
                                                  P1S, P1D, POOL, CNT, DEG, LOOK);
    {
        int gx = cdiv(n, 8);
        if (gx < cdiv(e, 256)) gx = cdiv(e, 256);
        dim3 gs(gx, 4);
        stage1_kernel<<<gs, 256>>>(x1, x2, P1S, P1D, AS, AD, X16,
                                   ei1, ei2, DEG, EIDX, n, e);
    }
    {
        dim3 gs2(nb, 2);
        scan_lookback_kernel<<<gs2, 256>>>(DEG, ROWPTR, LOOK, n, nb);
    }
    {
        dim3 ge2(cdiv(e, 256), 2);
        fill_kernel<<<ge2, 256>>>(ei1, ei2, ROWPTR, EIDX, ECOL, e);
    }
    {
        dim3 ga(cdiv(n, 8), 2);
        agg_x_kernel<<<ga, 256>>>(ROWPTR, ECOL, AS, AD, X16, AGG, n);
    }
    {
        dim3 gg(cdiv(n, 128), 2);
        gemm_fused_kernel<<<gg, 256, SMF_TOTAL>>>(AGG, W1TH, W1TL, b1,
                                                  W2TH, W2TL, H2,
                                                  as2, ad2, AS, AD, n);
    }
    {
        dim3 ga(cdiv(n, 8), 2);
        agg2_pool_kernel<<<ga, 256>>>(ROWPTR, ECOL, AS, AD, H2, b2,
                                      bt1, bt2, POOL, CNT, n);
    }
    final_write_kernel<<<cdiv(2 * GNUM * 64, 256), 256>>>(POOL, CNT, (float*)d_out);
}

// round 17
// speedup vs baseline: 1.7540x; 1.0312x over previous
#include <cuda_runtime.h>
#include <cuda_bf16.h>
#include <cstdint>

// ---------------------------------------------------------------------------
// GATGraphSimilarity: Siamese 2-layer GAT (heads=4 then 1) + mean pool.
// Round 17: L2-pollution control. All read-once/write-once bulk traffic uses
// streaming (evict-first) cache ops: AGG stores (st.global.cs), AGG loads in
// gemm (__ldcs), x loads in stage1 (__ldcs), eidx loads in fill (__ldcs).
// Keeps X16/H2/ecol/AS/weights L2-resident for the latency-bound gathers.
// ---------------------------------------------------------------------------

#define NMAX 50000
#define EMAX 800000
#define GNUM 64
#define NEG_SLOPE 0.2f
#define SCAN_CHUNK 4096
#define SCAN_NB ((NMAX + SCAN_CHUNK - 1) / SCAN_CHUNK)

__device__ __nv_bfloat16 g_X16[2][(size_t)NMAX * 128];
__device__ __nv_bfloat16 g_AGG[2][(size_t)NMAX * 512];
__device__ __nv_bfloat16 g_H2 [2][(size_t)NMAX * 64];
__device__ float g_AS  [2][NMAX * 4];
__device__ float g_AD  [2][NMAX * 4];
__device__ int   g_DEG [2][NMAX];
__device__ int   g_ROWPTR[2][NMAX + 1];
__device__ int   g_ECOL[2][EMAX];
__device__ int   g_EIDX[2][EMAX];
__device__ unsigned long long g_LOOK[2][SCAN_NB];
__device__ float g_POOL[2 * GNUM * 64];
__device__ float g_CNT [2 * GNUM];
__device__ float g_P1S [128 * 4];
__device__ float g_P1D [128 * 4];
__device__ __nv_bfloat16 g_W1T_HI[256 * 128];
__device__ __nv_bfloat16 g_W1T_LO[256 * 128];
__device__ __nv_bfloat16 g_W2T_HI[64 * 256];
__device__ __nv_bfloat16 g_W2T_LO[64 * 256];

static inline int cdiv(int a, int b) { return (a + b - 1) / b; }

__device__ __forceinline__ float leaky(float v) {
    return v > 0.0f ? v : NEG_SLOPE * v;
}

__device__ __forceinline__ uint32_t bf2u(__nv_bfloat162 v) {
    return *reinterpret_cast<uint32_t*>(&v);
}

// streaming (evict-first) 8-byte store to global
__device__ __forceinline__ void stcs_u2(void* p, uint2 v) {
    asm volatile("st.global.cs.v2.u32 [%0], {%1, %2};"
                 :: "l"(p), "r"(v.x), "r"(v.y) : "memory");
}

__device__ __forceinline__ void mma16816(float* d, const uint32_t* a, const uint32_t* b) {
    asm volatile(
        "mma.sync.aligned.m16n8k16.row.col.f32.bf16.bf16.f32 "
        "{%0,%1,%2,%3}, {%4,%5,%6,%7}, {%8,%9}, {%0,%1,%2,%3};"
        : "+f"(d[0]), "+f"(d[1]), "+f"(d[2]), "+f"(d[3])
        : "r"(a[0]), "r"(a[1]), "r"(a[2]), "r"(a[3]), "r"(b[0]), "r"(b[1]));
}

// ---------------------------------------------------------------------------
// Setup
// ---------------------------------------------------------------------------
#define SEG1 (256 * 128)
#define SEG2 (64 * 256)
#define SEG3 1024
#define SEG4 (2 * GNUM * 64 + 2 * GNUM)
#define SEG5 (2 * NMAX)
#define SEG6 (2 * SCAN_NB)
#define SETUP_TOTAL (SEG1 + SEG2 + SEG3 + SEG4 + SEG5 + SEG6)

__global__ void setup_kernel(const float* __restrict__ W1,
                             const float* __restrict__ W2,
                             const float* __restrict__ as1,
                             const float* __restrict__ ad1,
                             __nv_bfloat16* __restrict__ W1TH,
                             __nv_bfloat16* __restrict__ W1TL,
                             __nv_bfloat16* __restrict__ W2TH,
                             __nv_bfloat16* __restrict__ W2TL,
                             float* __restrict__ P1S,
                             float* __restrict__ P1D,
                             float* __restrict__ POOL,
                             float* __restrict__ CNT,
                             int* __restrict__ DEG,
                             unsigned long long* __restrict__ LOOK) {
    int i = blockIdx.x * blockDim.x + threadIdx.x;
    if (i < SEG1) {
        int n = i / 128, k = i % 128;
        float v = W1[(size_t)k * 256 + n];
        __nv_bfloat16 h = __float2bfloat16(v);
        W1TH[i] = h;
        W1TL[i] = __float2bfloat16(v - __bfloat162float(h));
        return;
    }
    i -= SEG1;
    if (i < SEG2) {
        int n = i / 256, k = i % 256;
        float v = W2[(size_t)k * 64 + n];
        __nv_bfloat16 h = __float2bfloat16(v);
        W2TH[i] = h;
        W2TL[i] = __float2bfloat16(v - __bfloat162float(h));
        return;
    }
    i -= SEG2;
    if (i < SEG3) {
        int is_dst = i >> 9;
        int o = i & 511;
        int k = o >> 2, h = o & 3;
        const float* a = is_dst ? ad1 : as1;
        float s = 0.0f;
        #pragma unroll 8
        for (int d = 0; d < 64; d++)
            s += W1[(size_t)k * 256 + h * 64 + d] * a[h * 64 + d];
        (is_dst ? P1D : P1S)[k * 4 + h] = s;
        return;
    }
    i -= SEG3;
    if (i < 2 * GNUM * 64) { POOL[i] = 0.0f; return; }
    i -= 2 * GNUM * 64;
    if (i < 2 * GNUM) { CNT[i] = 0.0f; return; }
    i -= 2 * GNUM;
    if (i < SEG5) { DEG[i] = 0; return; }
    i -= SEG5;
    if (i < SEG6) LOOK[i] = 0ULL;
}

// ---------------------------------------------------------------------------
// Stage1: alphas+X16 (parts 0,1); degree histogram + edge ranks (parts 2,3).
// ---------------------------------------------------------------------------
__global__ void stage1_kernel(const float* __restrict__ x0,
                              const float* __restrict__ x1,
                              const float* __restrict__ P1S,
                              const float* __restrict__ P1D,
                              float* __restrict__ AS,
                              float* __restrict__ AD,
                              __nv_bfloat16* __restrict__ X16,
                              const int* __restrict__ ei0,
                              const int* __restrict__ ei1,
                              int* __restrict__ deg,
                              int* __restrict__ eidx,
                              int n, int E) {
    const int part = blockIdx.y;
    if (part >= 2) {
        int g = part - 2;
        const int* ei = g ? ei1 : ei0;
        int i = blockIdx.x * blockDim.x + threadIdx.x;
        if (i < E) {
            int rank = atomicAdd(&deg[g * NMAX + ei[E + i]], 1);
            eidx[(size_t)g * EMAX + i] = rank;
        }
        return;
    }
    const int g = part;
    const float* x = g ? x1 : x0;
    const int warp = (blockIdx.x * blockDim.x + threadIdx.x) >> 5;
    const int lane = threadIdx.x & 31;
    if (warp >= n) return;
    float4 xv = __ldcs((const float4*)&x[(size_t)warp * 128 + lane * 4]);  // read-once
    {
        __nv_bfloat162 p0 = __floats2bfloat162_rn(xv.x, xv.y);
        __nv_bfloat162 p1 = __floats2bfloat162_rn(xv.z, xv.w);
        uint2 u = make_uint2(bf2u(p0), bf2u(p1));
        *(uint2*)&X16[(size_t)g * NMAX * 128 + (size_t)warp * 128 + lane * 4] = u;
    }
    float s[4] = {0.f, 0.f, 0.f, 0.f};
    float d[4] = {0.f, 0.f, 0.f, 0.f};
    const float* xp = (const float*)&xv;
    #pragma unroll
    for (int j = 0; j < 4; j++) {
        float xk = xp[j];
        float4 ps = *(const float4*)&P1S[(lane * 4 + j) * 4];
        float4 pd = *(const float4*)&P1D[(lane * 4 + j) * 4];
        s[0] += xk * ps.x; s[1] += xk * ps.y; s[2] += xk * ps.z; s[3] += xk * ps.w;
        d[0] += xk * pd.x; d[1] += xk * pd.y; d[2] += xk * pd.z; d[3] += xk * pd.w;
    }
    #pragma unroll
    for (int off = 16; off >= 1; off >>= 1) {
        #pragma unroll
        for (int h = 0; h < 4; h++) {
            s[h] += __shfl_xor_sync(0xffffffffu, s[h], off);
            d[h] += __shfl_xor_sync(0xffffffffu, d[h], off);
        }
    }
    if (lane == 0) {
        *(float4*)&AS[(size_t)g * NMAX * 4 + warp * 4] = make_float4(s[0], s[1], s[2], s[3]);
        *(float4*)&AD[(size_t)g * NMAX * 4 + warp * 4] = make_float4(d[0], d[1], d[2], d[3]);
    }
}

// ---------------------------------------------------------------------------
// Decoupled-lookback scan: deg -> rowptr (exclusive).
// ---------------------------------------------------------------------------
__global__ void scan_lookback_kernel(const int* __restrict__ deg,
                                     int* __restrict__ rowptr,
                                     unsigned long long* __restrict__ LOOK,
                                     int n, int nb) {
    __shared__ int thr[256];
    __shared__ int sh_P;
    const int g = blockIdx.y;
    const int b = blockIdx.x;
    const int t = threadIdx.x;
    const int base = b * SCAN_CHUNK + t * 16;
    const int* dg = deg + g * NMAX;
    int* rp = rowptr + g * (NMAX + 1);
    unsigned long long* look = LOOK + g * SCAN_NB;

    int s = 0;
    int dloc[16];
    #pragma unroll
    for (int q = 0; q < 16; q++) {
        int i = base + q;
        dloc[q] = (i < n) ? dg[i] : 0;
        s += dloc[q];
    }
    thr[t] = s;
    __syncthreads();
    #pragma unroll
    for (int off = 1; off < 256; off <<= 1) {
        int v = (t >= off) ? thr[t - off] : 0;
        __syncthreads();
        thr[t] += v;
        __syncthreads();
    }
    const int total = thr[255];

    if (t == 0) {
        int P = 0;
        if (b == 0) {
            atomicExch(&look[0], (2ULL << 32) | (unsigned int)total);
        } else {
            atomicExch(&look[b], (1ULL << 32) | (unsigned int)total);
            int i = b - 1;
            while (true) {
                unsigned long long w;
                do { w = atomicAdd(&look[i], 0ULL); } while ((w >> 32) == 0ULL);
                int v = (int)(w & 0xffffffffULL);
                P += v;
                if ((w >> 32) == 2ULL) break;
                i--;
            }
            atomicExch(&look[b], (2ULL << 32) | (unsigned int)(P + total));
        }
        sh_P = P;
    }
    __syncthreads();

    int offset = sh_P + ((t == 0) ? 0 : thr[t - 1]);
    #pragma unroll
    for (int q = 0; q < 16; q++) {
        int i = base + q;
        if (i < n) {
            rp[i] = offset;
            offset += dloc[q];
        }
    }
    if (b == nb - 1 && t == 255) rp[n] = offset;
}

// fill CSR: atomic-free scatter using precomputed ranks
__global__ void fill_kernel(const int* __restrict__ ei0, const int* __restrict__ ei1,
                            const int* __restrict__ rowptr,
                            const int* __restrict__ eidx,
                            int* __restrict__ ecol, int E) {
    int g = blockIdx.y;
    const int* ei = g ? ei1 : ei0;
    int i = blockIdx.x * blockDim.x + threadIdx.x;
    if (i >= E) return;
    int s = ei[i];
    int d = ei[E + i];
    int rank = __ldcs(&eidx[(size_t)g * EMAX + i]);   // read-once
    int slot = rowptr[g * (NMAX + 1) + d] + rank;
    ecol[(size_t)g * EMAX + slot] = s;
}

// ---------------------------------------------------------------------------
// conv1 aggregation: smem-staged lane-parallel edge weights, then gather+FMA.
// AGG written with streaming stores (read exactly once by gemm).
// ---------------------------------------------------------------------------
__global__ void agg_x_kernel(const int* __restrict__ rowptr,
                             const int* __restrict__ ecol,
                             const float* __restrict__ AS,
                             const float* __restrict__ AD,
                             const __nv_bfloat16* __restrict__ X16,
                             __nv_bfloat16* __restrict__ AGG,
                             int n) {
    __shared__ int    sh_s[8][32];
    __shared__ float4 sh_u[8][32];

    const int g = blockIdx.y;
    const int* rp = rowptr + g * (NMAX + 1);
    const int* ec = ecol + (size_t)g * EMAX;
    const float* as = AS + (size_t)g * NMAX * 4;
    const __nv_bfloat16* X = X16 + (size_t)g * NMAX * 128;
    __nv_bfloat16* agg = AGG + (size_t)g * NMAX * 512;

    const int w = threadIdx.x >> 5;
    const int warp = (blockIdx.x * blockDim.x + threadIdx.x) >> 5;
    const int lane = threadIdx.x & 31;
    if (warp >= n) return;
    const int d = warp;
    const int beg = rp[d];
    const int end = rp[d + 1];

    float4 asv = *(const float4*)&as[d * 4];
    float4 adv = *(const float4*)&AD[(size_t)g * NMAX * 4 + d * 4];
    float den[4];
    den[0] = __expf(leaky(asv.x + adv.x));
    den[1] = __expf(leaky(asv.y + adv.y));
    den[2] = __expf(leaky(asv.z + adv.z));
    den[3] = __expf(leaky(asv.w + adv.w));

    uint2 ux = *(const uint2*)&X[(size_t)d * 128 + lane * 4];
    float2 xd01 = __bfloat1622float2(*(__nv_bfloat162*)&ux.x);
    float2 xd23 = __bfloat1622float2(*(__nv_bfloat162*)&ux.y);

    float acc[4][4];
    #pragma unroll
    for (int h = 0; h < 4; h++) {
        acc[h][0] = den[h] * xd01.x; acc[h][1] = den[h] * xd01.y;
        acc[h][2] = den[h] * xd23.x; acc[h][3] = den[h] * xd23.y;
    }

    for (int jb = beg; jb < end; jb += 32) {
        int m = end - jb;
        if (m > 32) m = 32;
        if (lane < m) {
            int s = ec[jb + lane];
            float4 a = *(const float4*)&as[s * 4];
            float4 u;
            u.x = __expf(leaky(a.x + adv.x));
            u.y = __expf(leaky(a.y + adv.y));
            u.z = __expf(leaky(a.z + adv.z));
            u.w = __expf(leaky(a.w + adv.w));
            sh_s[w][lane] = s;
            sh_u[w][lane] = u;
        }
        __syncwarp();
        #pragma unroll 4
        for (int k = 0; k < m; k++) {
            int ss = sh_s[w][k];
            float4 u = sh_u[w][k];
            den[0] += u.x; den[1] += u.y; den[2] += u.z; den[3] += u.w;
            uint2 q = *(const uint2*)&X[(size_t)ss * 128 + lane * 4];
            float2 f01 = __bfloat1622float2(*(__nv_bfloat162*)&q.x);
            float2 f23 = __bfloat1622float2(*(__nv_bfloat162*)&q.y);
            acc[0][0] += u.x * f01.x; acc[0][1] += u.x * f01.y;
            acc[0][2] += u.x * f23.x; acc[0][3] += u.x * f23.y;
            acc[1][0] += u.y * f01.x; acc[1][1] += u.y * f01.y;
            acc[1][2] += u.y * f23.x; acc[1][3] += u.y * f23.y;
            acc[2][0] += u.z * f01.x; acc[2][1] += u.z * f01.y;
            acc[2][2] += u.z * f23.x; acc[2][3] += u.z * f23.y;
            acc[3][0] += u.w * f01.x; acc[3][1] += u.w * f01.y;
            acc[3][2] += u.w * f23.x; acc[3][3] += u.w * f23.y;
        }
        __syncwarp();
    }

    #pragma unroll
    for (int h = 0; h < 4; h++) {
        float inv = 1.0f / (den[h] + 1e-16f);
        __nv_bfloat162 q0 = __floats2bfloat162_rn(acc[h][0] * inv, acc[h][1] * inv);
        __nv_bfloat162 q1 = __floats2bfloat162_rn(acc[h][2] * inv, acc[h][3] * inv);
        uint2 u = make_uint2(bf2u(q0), bf2u(q1));
        stcs_u2(&agg[(size_t)d * 512 + h * 128 + lane * 4], u);  // streaming store
    }
}

// ---------------------------------------------------------------------------
// FUSED GEMM, 87KB smem (B1/O overlay, O stored hi-only for gemm2).
// AGG read with __ldcs (read-once).
// ---------------------------------------------------------------------------
#define SMF_A     0
#define SMF_REG   34816
#define SMF_B1H   (SMF_REG)
#define SMF_B1L   (SMF_REG + 17408)
#define SMF_OH    (SMF_REG)
#define SMF_B2H   (SMF_REG + 34816)
#define SMF_B2L   (SMF_B2H + 9216)
#define SMF_ALPHA (SMF_B2H + 18432)
#define SMF_TOTAL (SMF_ALPHA + 1024)      // 88064

__global__ __launch_bounds__(256, 2)
void gemm_fused_kernel(const __nv_bfloat16* __restrict__ AGG,
                       const __nv_bfloat16* __restrict__ B1hi,
                       const __nv_bfloat16* __restrict__ B1lo,
                       const float* __restrict__ bias1,
                       const __nv_bfloat16* __restrict__ B2hi,
                       const __nv_bfloat16* __restrict__ B2lo,
                       __nv_bfloat16* __restrict__ H2,
                       const float* __restrict__ a_src,
                       const float* __restrict__ a_dst,
                       float* __restrict__ AS,
                       float* __restrict__ AD,
                       int M) {
    extern __shared__ char smem[];
    uint32_t* Asm = (uint32_t*)(smem + SMF_A);
    uint32_t* B1h = (uint32_t*)(smem + SMF_B1H);
    uint32_t* B1l = (uint32_t*)(smem + SMF_B1L);
    uint32_t* Oh  = (uint32_t*)(smem + SMF_OH);
    uint32_t* B2h = (uint32_t*)(smem + SMF_B2H);
    uint32_t* B2l = (uint32_t*)(smem + SMF_B2L);
    float* alpha_s = (float*)(smem + SMF_ALPHA);
    float* alpha_d = alpha_s + 128;

    const int g = blockIdx.y;
    const __nv_bfloat16* A = AGG + (size_t)g * NMAX * 512;
    __nv_bfloat16* C = H2 + (size_t)g * NMAX * 64;
    float* ASg = AS + (size_t)g * NMAX * 4;
    float* ADg = AD + (size_t)g * NMAX * 4;
    const int tid = threadIdx.x;
    const int lane = tid & 31;
    const int wid = tid >> 5;
    const int warp_m = wid & 3;
    const int warp_n = wid >> 2;
    const int m0 = blockIdx.x * 128;

    float acc2[2][4][4] = {};

    for (int h = 0; h < 4; h++) {
        if (h) __syncthreads();

        #pragma unroll
        for (int q = 0; q < 8; q++) {
            int idx = q * 256 + tid;
            int r = idx >> 4;
            int c8 = idx & 15;
            int gr = m0 + r;
            uint4 v = make_uint4(0u, 0u, 0u, 0u);
            if (gr < M) v = __ldcs((const uint4*)&A[(size_t)gr * 512 + h * 128 + c8 * 8]);
            *(uint4*)&Asm[r * 68 + c8 * 4] = v;
        }
        #pragma unroll
        for (int q = 0; q < 4; q++) {
            int idx = q * 256 + tid;
            int r = idx >> 4;
            int c8 = idx & 15;
            uint4 vh = *(const uint4*)&B1hi[(size_t)(h * 64 + r) * 128 + c8 * 8];
            uint4 vl = *(const uint4*)&B1lo[(size_t)(h * 64 + r) * 128 + c8 * 8];
            *(uint4*)&B1h[r * 68 + c8 * 4] = vh;
            *(uint4*)&B1l[r * 68 + c8 * 4] = vl;
        }
        #pragma unroll
        for (int q = 0; q < 2; q++) {
            int idx = q * 256 + tid;
            int r = idx >> 3;
            int c8 = idx & 7;
            uint4 vh = *(const uint4*)&B2hi[(size_t)r * 256 + h * 64 + c8 * 8];
            uint4 vl = *(const uint4*)&B2lo[(size_t)r * 256 + h * 64 + c8 * 8];
            *(uint4*)&B2h[r * 36 + c8 * 4] = vh;
            *(uint4*)&B2l[r * 36 + c8 * 4] = vl;
        }
        __syncthreads();

        // gemm1: acc1 = A @ B1 (2-term, weight split kept)
        float acc1[2][4][4] = {};
        #pragma unroll
        for (int ks = 0; ks < 8; ks++) {
            const int kw = ks * 8 + (lane & 3);
            uint32_t ah[2][4], bh[4][2], bl[4][2];
            #pragma unroll
            for (int mt = 0; mt < 2; mt++) {
                int r0 = warp_m * 32 + mt * 16 + (lane >> 2);
                ah[mt][0] = Asm[r0 * 68 + kw];
                ah[mt][1] = Asm[(r0 + 8) * 68 + kw];
                ah[mt][2] = Asm[r0 * 68 + kw + 4];
                ah[mt][3] = Asm[(r0 + 8) * 68 + kw + 4];
            }
            #pragma unroll
            for (int nt = 0; nt < 4; nt++) {
                int n0 = warp_n * 32 + nt * 8 + (lane >> 2);
                bh[nt][0] = B1h[n0 * 68 + kw];
                bh[nt][1] = B1h[n0 * 68 + kw + 4];
                bl[nt][0] = B1l[n0 * 68 + kw];
                bl[nt][1] = B1l[n0 * 68 + kw + 4];
            }
            #pragma unroll
            for (int mt = 0; mt < 2; mt++)
                #pragma unroll
                for (int nt = 0; nt < 4; nt++) {
                    mma16816(acc1[mt][nt], ah[mt], bh[nt]);
                    mma16816(acc1[mt][nt], ah[mt], bl[nt]);
                }
        }
        __syncthreads();   // B1 reads complete before O overwrites the region

        // bias + ELU, bf16 hi into O (overlaying B1)
        #pragma unroll
        for (int mt = 0; mt < 2; mt++) {
            int r0 = warp_m * 32 + mt * 16 + (lane >> 2);
            #pragma unroll
            for (int nt = 0; nt < 4; nt++) {
                int c0 = warp_n * 32 + nt * 8 + (lane & 3) * 2;
                float b0 = __ldg(&bias1[h * 64 + c0]);
                float b1v = __ldg(&bias1[h * 64 + c0 + 1]);
                float* a4 = acc1[mt][nt];
                float v00 = a4[0] + b0, v01 = a4[1] + b1v;
                float v10 = a4[2] + b0, v11 = a4[3] + b1v;
                v00 = v00 > 0.f ? v00 : (__expf(v00) - 1.f);
                v01 = v01 > 0.f ? v01 : (__expf(v01) - 1.f);
                v10 = v10 > 0.f ? v10 : (__expf(v10) - 1.f);
                v11 = v11 > 0.f ? v11 : (__expf(v11) - 1.f);
                int w = warp_n * 16 + nt * 4 + (lane & 3);
                Oh[r0 * 36 + w] = bf2u(__floats2bfloat162_rn(v00, v01));
                Oh[(r0 + 8) * 36 + w] = bf2u(__floats2bfloat162_rn(v10, v11));
            }
        }
        __syncthreads();

        // gemm2 accumulate: acc2 += Oh @ (B2h + B2l)
        #pragma unroll
        for (int ks = 0; ks < 4; ks++) {
            const int kw = ks * 8 + (lane & 3);
            uint32_t aoh[2][4], bh[4][2], bl[4][2];
            #pragma unroll
            for (int mt = 0; mt < 2; mt++) {
                int r0 = warp_m * 32 + mt * 16 + (lane >> 2);
                aoh[mt][0] = Oh[r0 * 36 + kw];
                aoh[mt][1] = Oh[(r0 + 8) * 36 + kw];
                aoh[mt][2] = Oh[r0 * 36 + kw + 4];
                aoh[mt][3] = Oh[(r0 + 8) * 36 + kw + 4];
            }
            #pragma unroll
            for (int nt = 0; nt < 4; nt++) {
                int n0 = warp_n * 32 + nt * 8 + (lane >> 2);
                bh[nt][0] = B2h[n0 * 36 + kw];
                bh[nt][1] = B2h[n0 * 36 + kw + 4];
                bl[nt][0] = B2l[n0 * 36 + kw];
                bl[nt][1] = B2l[n0 * 36 + kw + 4];
            }
            #pragma unroll
            for (int mt = 0; mt < 2; mt++)
                #pragma unroll
                for (int nt = 0; nt < 4; nt++) {
                    mma16816(acc2[mt][nt], aoh[mt], bh[nt]);
                    mma16816(acc2[mt][nt], aoh[mt], bl[nt]);
                }
        }
    }

    __syncthreads();
    if (tid < 128) { alpha_s[tid] = 0.0f; alpha_d[tid] = 0.0f; }
    __syncthreads();

    float sp[4] = {0.f, 0.f, 0.f, 0.f};
    float dp[4] = {0.f, 0.f, 0.f, 0.f};
    #pragma unroll
    for (int mt = 0; mt < 2; mt++) {
        int r0 = warp_m * 32 + mt * 16 + (lane >> 2);
        #pragma unroll
        for (int nt = 0; nt < 4; nt++) {
            int c0 = warp_n * 32 + nt * 8 + (lane & 3) * 2;
            float* a4 = acc2[mt][nt];
            int gr0 = m0 + r0, gr1 = gr0 + 8;
            if (gr0 < M)
                *(__nv_bfloat162*)&C[(size_t)gr0 * 64 + c0] = __floats2bfloat162_rn(a4[0], a4[1]);
            if (gr1 < M)
                *(__nv_bfloat162*)&C[(size_t)gr1 * 64 + c0] = __floats2bfloat162_rn(a4[2], a4[3]);
            float s0 = __ldg(&a_src[c0]);
            float s1 = __ldg(&a_src[c0 + 1]);
            float d0 = __ldg(&a_dst[c0]);
            float d1 = __ldg(&a_dst[c0 + 1]);
            sp[mt * 2]     += a4[0] * s0 + a4[1] * s1;
            sp[mt * 2 + 1] += a4[2] * s0 + a4[3] * s1;
            dp[mt * 2]     += a4[0] * d0 + a4[1] * d1;
            dp[mt * 2 + 1] += a4[2] * d0 + a4[3] * d1;
        }
    }
    #pragma unroll
    for (int i = 0; i < 4; i++) {
        sp[i] += __shfl_xor_sync(0xffffffffu, sp[i], 1);
        sp[i] += __shfl_xor_sync(0xffffffffu, sp[i], 2);
        dp[i] += __shfl_xor_sync(0xffffffffu, dp[i], 1);
        dp[i] += __shfl_xor_sync(0xffffffffu, dp[i], 2);
    }
    if ((lane & 3) == 0) {
        int r0 = warp_m * 32 + (lane >> 2);
        atomicAdd(&alpha_s[r0],      sp[0]);
        atomicAdd(&alpha_s[r0 + 8],  sp[1]);
        atomicAdd(&alpha_s[r0 + 16], sp[2]);
        atomicAdd(&alpha_s[r0 + 24], sp[3]);
        atomicAdd(&alpha_d[r0],      dp[0]);
        atomicAdd(&alpha_d[r0 + 8],  dp[1]);
        atomicAdd(&alpha_d[r0 + 16], dp[2]);
        atomicAdd(&alpha_d[r0 + 24], dp[3]);
    }
    __syncthreads();
    if (tid < 128) {
        int gr = m0 + tid;
        if (gr < M) {
            ASg[gr * 4] = alpha_s[tid];
            ADg[gr * 4] = alpha_d[tid];
        }
    }
}

// ---------------------------------------------------------------------------
// conv2 aggregation with in-warp lane-parallel edge weights + mean pool.
// ---------------------------------------------------------------------------
__global__ void agg2_pool_kernel(const int* __restrict__ rowptr,
                                 const int* __restrict__ ecol,
                                 const float* __restrict__ AS,
                                 const float* __restrict__ AD,
                                 const __nv_bfloat16* __restrict__ H2,
                                 const float* __restrict__ bias,
                                 const int* __restrict__ bt0,
                                 const int* __restrict__ bt1,
                                 float* __restrict__ POOL,
                                 float* __restrict__ CNT,
                                 int n) {
    const int g = blockIdx.y;
    const int* rp = rowptr + g * (NMAX + 1);
    const int* ec = ecol + (size_t)g * EMAX;
    const float* as = AS + (size_t)g * NMAX * 4;
    const __nv_bfloat16* H = H2 + (size_t)g * NMAX * 64;
    const int* batch = g ? bt1 : bt0;
    float* pool = POOL + g * GNUM * 64;
    float* cnt = CNT + g * GNUM;

    const int warp = (blockIdx.x * blockDim.x + threadIdx.x) >> 5;
    const int lane = threadIdx.x & 31;
    if (warp >= n) return;
    const int d = warp;
    const int beg = rp[d];
    const int end = rp[d + 1];

    float ad_d = AD[(size_t)g * NMAX * 4 + d * 4];
    float den = __expf(leaky(as[d * 4] + ad_d));
    float2 hv = __bfloat1622float2(*(const __nv_bfloat162*)&H[(size_t)d * 64 + lane * 2]);
    float a0 = den * hv.x, a1 = den * hv.y;

    for (int jb = beg; jb < end; jb += 32) {
        int m = end - jb;
        if (m > 32) m = 32;
        int s = 0;
        float u = 0.0f;
        if (lane < m) {
            s = ec[jb + lane];
            u = __expf(leaky(as[s * 4] + ad_d));
        }
        #pragma unroll 4
        for (int k = 0; k < m; k++) {
            int ss = __shfl_sync(0xffffffffu, s, k);
            float uk = __shfl_sync(0xffffffffu, u, k);
            den += uk;
            float2 hs = __bfloat1622float2(*(const __nv_bfloat162*)&H[(size_t)ss * 64 + lane * 2]);
            a0 += uk * hs.x;
            a1 += uk * hs.y;
        }
    }
    float inv = 1.0f / (den + 1e-16f);
    float v0 = a0 * inv + bias[lane * 2];
    float v1 = a1 * inv + bias[lane * 2 + 1];
    v0 = v0 > 0.0f ? v0 : (__expf(v0) - 1.0f);
    v1 = v1 > 0.0f ? v1 : (__expf(v1) - 1.0f);
    int grp = batch[d];
    atomicAdd(&pool[grp * 64 + lane * 2], v0);
    atomicAdd(&pool[grp * 64 + lane * 2 + 1], v1);
    if (lane == 0) atomicAdd(&cnt[grp], 1.0f);
}

__global__ void final_write_kernel(const float* __restrict__ POOL,
                                   const float* __restrict__ CNT,
                                   float* __restrict__ out) {
    int i = blockIdx.x * blockDim.x + threadIdx.x;
    if (i >= 2 * GNUM * 64) return;
    float c = CNT[i >> 6];
    out[i] = POOL[i] / fmaxf(c, 1.0f);
}

// ---------------------------------------------------------------------------
// Launch
// ---------------------------------------------------------------------------
extern "C" void kernel_launch(void* const* d_in, const int* in_sizes, int n_in,
                              void* d_out, int out_size) {
    const float* x1  = (const float*)d_in[0];
    const int*   ei1 = (const int*)d_in[1];
    const int*   bt1 = (const int*)d_in[2];
    const float* x2  = (const float*)d_in[3];
    const int*   ei2 = (const int*)d_in[4];
    const int*   bt2 = (const int*)d_in[5];
    const float* W1  = (const float*)d_in[6];
    const float* as1 = (const float*)d_in[7];
    const float* ad1 = (const float*)d_in[8];
    const float* b1  = (const float*)d_in[9];
    const float* W2  = (const float*)d_in[10];
    const float* as2 = (const float*)d_in[11];
    const float* ad2 = (const float*)d_in[12];
    const float* b2  = (const float*)d_in[13];

    const int n = in_sizes[0] / 128;
    const int e = in_sizes[1] / 2;
    const int nb = cdiv(n, SCAN_CHUNK);

    float *AS, *AD, *POOL, *CNT, *P1S, *P1D;
    int *DEG, *ROWPTR, *ECOL, *EIDX;
    unsigned long long* LOOK;
    __nv_bfloat16 *X16, *AGG, *H2, *W1TH, *W1TL, *W2TH, *W2TL;
    cudaGetSymbolAddress((void**)&X16,    g_X16);
    cudaGetSymbolAddress((void**)&AGG,    g_AGG);
    cudaGetSymbolAddress((void**)&H2,     g_H2);
    cudaGetSymbolAddress((void**)&AS,     g_AS);
    cudaGetSymbolAddress((void**)&AD,     g_AD);
    cudaGetSymbolAddress((void**)&DEG,    g_DEG);
    cudaGetSymbolAddress((void**)&ROWPTR, g_ROWPTR);
    cudaGetSymbolAddress((void**)&ECOL,   g_ECOL);
    cudaGetSymbolAddress((void**)&EIDX,   g_EIDX);
    cudaGetSymbolAddress((void**)&LOOK,   g_LOOK);
    cudaGetSymbolAddress((void**)&POOL,   g_POOL);
    cudaGetSymbolAddress((void**)&CNT,    g_CNT);
    cudaGetSymbolAddress((void**)&P1S,    g_P1S);
    cudaGetSymbolAddress((void**)&P1D,    g_P1D);
    cudaGetSymbolAddress((void**)&W1TH,   g_W1T_HI);
    cudaGetSymbolAddress((void**)&W1TL,   g_W1T_LO);
    cudaGetSymbolAddress((void**)&W2TH,   g_W2T_HI);
    cudaGetSymbolAddress((void**)&W2TL,   g_W2T_LO);

    cudaFuncSetAttribute(gemm_fused_kernel,
                         cudaFuncAttributeMaxDynamicSharedMemorySize, SMF_TOTAL);

    setup_kernel<<<cdiv(SETUP_TOTAL, 256), 256>>>(W1, W2, as1, ad1,
                                                  W1TH, W1TL, W2TH, W2TL,
                                                  P1S, P1D, POOL, CNT, DEG, LOOK);
    {
        int gx = cdiv(n, 8);
        if (gx < cdiv(e, 256)) gx = cdiv(e, 256);
        dim3 gs(gx, 4);
        stage1_kernel<<<gs, 256>>>(x1, x2, P1S, P1D, AS, AD, X16,
                                   ei1, ei2, DEG, EIDX, n, e);
    }
    {
        dim3 gs2(nb, 2);
        scan_lookback_kernel<<<gs2, 256>>>(DEG, ROWPTR, LOOK, n, nb);
    }
    {
        dim3 ge2(cdiv(e, 256), 2);
        fill_kernel<<<ge2, 256>>>(ei1, ei2, ROWPTR, EIDX, ECOL, e);
    }
    {
        dim3 ga(cdiv(n, 8), 2);
        agg_x_kernel<<<ga, 256>>>(ROWPTR, ECOL, AS, AD, X16, AGG, n);
    }
    {
        dim3 gg(cdiv(n, 128), 2);
        gemm_fused_kernel<<<gg, 256, SMF_TOTAL>>>(AGG, W1TH, W1TL, b1,
                                                  W2TH, W2TL, H2,
                                                  as2, ad2, AS, AD, n);
    }
    {
        dim3 ga(cdiv(n, 8), 2);
        agg2_pool_kernel<<<ga, 256>>>(ROWPTR, ECOL, AS, AD, H2, b2,
                                      bt1, bt2, POOL, CNT, n);
    }
    final_write_kernel<<<cdiv(2 * GNUM * 64, 256), 256>>>(POOL, CNT, (float*)d_out);
}